// round 9
// baseline (speedup 1.0000x reference)
#include <cuda_runtime.h>
#include <cuda_bf16.h>
#include <cstdint>

// ---------------------------------------------------------------------------
// MultiHead2DAttention (Shaw relative positions, T2T variant)
// B=2, L=1024, D=1024, H=16, DH=64, M=64, R=129
// Round 8: FULL attention fusion. One kernel does logits + softmax + wsum +
// A@V + rel_v epilogue per (bh, 32-row block). The 128MB score matrix and
// g_wsum are never materialized in global memory. GEMMs unchanged (mma.sync
// compensated bf16).
// ---------------------------------------------------------------------------

namespace {
constexpr int B  = 2;
constexpr int L  = 1024;
constexpr int D  = 1024;
constexpr int H  = 16;
constexpr int DH = 64;
constexpr int MREL = 64;
constexpr int R  = 2 * MREL + 1;   // 129
constexpr int RP = 132;            // padded row stride for relq
constexpr int NT = B * L;          // 2048
constexpr int BH = B * H;          // 32
}

typedef __nv_bfloat16 bf16;
typedef unsigned long long u64;
typedef unsigned int u32;

// Scratch buffers (device globals: no allocations allowed)
__device__ float g_q[NT * D];
__device__ float g_k[NT * D];
__device__ float g_v[NT * D];
__device__ float g_o[NT * D];
__device__ float g_relq[(size_t)BH * L * RP];

// bf16 split buffers
__device__ bf16 g_xh[NT * D];
__device__ bf16 g_xl[NT * D];
__device__ bf16 g_wh[D * D];     // transposed [N][K]
__device__ bf16 g_wl[D * D];

// ---------------------------------------------------------------------------
// packed fp32 helpers
// ---------------------------------------------------------------------------
__device__ __forceinline__ u64 pk2(float x, float y) {
    u64 r;
    asm("mov.b64 %0, {%1, %2};" : "=l"(r) : "f"(x), "f"(y));
    return r;
}
__device__ __forceinline__ u64 dup2(float x) { return pk2(x, x); }
__device__ __forceinline__ u64 ffma2(u64 a, u64 b, u64 c) {
    u64 d;
    asm("fma.rn.f32x2 %0, %1, %2, %3;" : "=l"(d) : "l"(a), "l"(b), "l"(c));
    return d;
}
__device__ __forceinline__ float2 up2(u64 v) {
    float2 f;
    asm("mov.b64 {%0, %1}, %2;" : "=f"(f.x), "=f"(f.y) : "l"(v));
    return f;
}

// ---------------------------------------------------------------------------
// mma helper: D(f32) += A(bf16 16x16) * B(bf16 16x8)
// ---------------------------------------------------------------------------
__device__ __forceinline__ void mma16816(float* c, const u32* a, const u32* b) {
    asm volatile(
        "mma.sync.aligned.m16n8k16.row.col.f32.bf16.bf16.f32 "
        "{%0,%1,%2,%3},{%4,%5,%6,%7},{%8,%9},{%0,%1,%2,%3};"
        : "+f"(c[0]), "+f"(c[1]), "+f"(c[2]), "+f"(c[3])
        : "r"(a[0]), "r"(a[1]), "r"(a[2]), "r"(a[3]), "r"(b[0]), "r"(b[1]));
}

__device__ __forceinline__ void cp16(u32 smem_addr, const void* gptr) {
    asm volatile("cp.async.cg.shared.global [%0], [%1], 16;"
                 :: "r"(smem_addr), "l"(gptr));
}

// ---------------------------------------------------------------------------
// split: src fp32 -> hi/lo bf16 (elementwise)
// ---------------------------------------------------------------------------
__global__ __launch_bounds__(256) void split_kernel(const float* __restrict__ src,
                                                    bf16* __restrict__ hi,
                                                    bf16* __restrict__ lo) {
    int i = (blockIdx.x * 256 + threadIdx.x) * 4;
    float4 v = *(const float4*)(src + i);
    bf16 h0 = __float2bfloat16(v.x);
    bf16 h1 = __float2bfloat16(v.y);
    bf16 h2 = __float2bfloat16(v.z);
    bf16 h3 = __float2bfloat16(v.w);
    bf16 l0 = __float2bfloat16(v.x - __bfloat162float(h0));
    bf16 l1 = __float2bfloat16(v.y - __bfloat162float(h1));
    bf16 l2 = __float2bfloat16(v.z - __bfloat162float(h2));
    bf16 l3 = __float2bfloat16(v.w - __bfloat162float(h3));
    __nv_bfloat162* hp = (__nv_bfloat162*)(hi + i);
    __nv_bfloat162* lp = (__nv_bfloat162*)(lo + i);
    hp[0] = __nv_bfloat162(h0, h1);
    hp[1] = __nv_bfloat162(h2, h3);
    lp[0] = __nv_bfloat162(l0, l1);
    lp[1] = __nv_bfloat162(l2, l3);
}

// ---------------------------------------------------------------------------
// splitT: W[K][N] fp32 -> transposed hi/lo bf16 [N][K]
// ---------------------------------------------------------------------------
__global__ void splitT_kernel(const float* __restrict__ W,
                              bf16* __restrict__ th, bf16* __restrict__ tl) {
    __shared__ float ts[32][33];
    const int tx = threadIdx.x, ty = threadIdx.y;
    const int n0 = blockIdx.x * 32, k0 = blockIdx.y * 32;
    for (int r = ty; r < 32; r += 8)
        ts[r][tx] = W[(size_t)(k0 + r) * D + n0 + tx];
    __syncthreads();
    for (int r = ty; r < 32; r += 8) {
        float v = ts[tx][r];
        bf16 h = __float2bfloat16(v);
        bf16 l = __float2bfloat16(v - __bfloat162float(h));
        th[(size_t)(n0 + r) * D + k0 + tx] = h;
        tl[(size_t)(n0 + r) * D + k0 + tx] = l;
    }
}

// ---------------------------------------------------------------------------
// hgemm3x: C[M,N] = alpha * A[M,K] @ B[K,N]  (unchanged, known-good)
// ---------------------------------------------------------------------------
__global__ __launch_bounds__(256) void hgemm3x(const bf16* __restrict__ Ah,
                                               const bf16* __restrict__ Al,
                                               const bf16* __restrict__ Bh,
                                               const bf16* __restrict__ Bl,
                                               float* __restrict__ C,
                                               int Md, int Nd, int Kd,
                                               float alpha) {
    constexpr int STR = 24;
    constexpr int STG = 128 * STR;
    __shared__ bf16 As_h[2 * STG];
    __shared__ bf16 As_l[2 * STG];
    __shared__ bf16 Bs_h[2 * STG];
    __shared__ bf16 Bs_l[2 * STG];

    const int tid = threadIdx.x;
    const int bm = blockIdx.y * 128;
    const int bn = blockIdx.x * 128;
    const int wid = tid >> 5;
    const int lane = tid & 31;
    const int g = lane >> 2;
    const int tg = lane & 3;
    const int wm = (wid & 1) * 64;
    const int wn = (wid >> 1) * 32;

    const int lrow = tid >> 1;
    const int lseg = (tid & 1) * 8;
    const size_t aoff = (size_t)(bm + lrow) * Kd + lseg;
    const size_t boff = (size_t)(bn + lrow) * Kd + lseg;
    const u32 sdst = (u32)(lrow * STR + lseg) * 2;
    const u32 s_ah = (u32)__cvta_generic_to_shared(As_h);
    const u32 s_al = (u32)__cvta_generic_to_shared(As_l);
    const u32 s_bh = (u32)__cvta_generic_to_shared(Bs_h);
    const u32 s_bl = (u32)__cvta_generic_to_shared(Bs_l);

    float acc[4][4][4];
#pragma unroll
    for (int ma = 0; ma < 4; ++ma)
#pragma unroll
        for (int na = 0; na < 4; ++na)
#pragma unroll
            for (int e = 0; e < 4; ++e) acc[ma][na][e] = 0.0f;

    const int nT = Kd / 16;

    {
        const u32 o = sdst;
        cp16(s_ah + o, Ah + aoff);
        cp16(s_al + o, Al + aoff);
        cp16(s_bh + o, Bh + boff);
        cp16(s_bl + o, Bl + boff);
        asm volatile("cp.async.commit_group;");
    }

    for (int kt = 0; kt < nT; ++kt) {
        const int stg = kt & 1;
        if (kt + 1 < nT) {
            const u32 o = (u32)((stg ^ 1) * STG * 2) + sdst;
            const size_t ko = (size_t)(kt + 1) * 16;
            cp16(s_ah + o, Ah + aoff + ko);
            cp16(s_al + o, Al + aoff + ko);
            cp16(s_bh + o, Bh + boff + ko);
            cp16(s_bl + o, Bl + boff + ko);
            asm volatile("cp.async.commit_group;");
            asm volatile("cp.async.wait_group 1;");
        } else {
            asm volatile("cp.async.wait_group 0;");
        }
        __syncthreads();

        const bf16* Abh = As_h + stg * STG;
        const bf16* Abl = As_l + stg * STG;
        const bf16* Bbh = Bs_h + stg * STG;
        const bf16* Bbl = Bs_l + stg * STG;

        u32 ah[4][4], al[4][4], bh[4][2], bl[4][2];
#pragma unroll
        for (int ma = 0; ma < 4; ++ma) {
            const int r0 = (wm + ma * 16 + g) * STR + 2 * tg;
            const int r1 = r0 + 8 * STR;
            ah[ma][0] = *(const u32*)(Abh + r0);
            ah[ma][1] = *(const u32*)(Abh + r1);
            ah[ma][2] = *(const u32*)(Abh + r0 + 8);
            ah[ma][3] = *(const u32*)(Abh + r1 + 8);
            al[ma][0] = *(const u32*)(Abl + r0);
            al[ma][1] = *(const u32*)(Abl + r1);
            al[ma][2] = *(const u32*)(Abl + r0 + 8);
            al[ma][3] = *(const u32*)(Abl + r1 + 8);
        }
#pragma unroll
        for (int na = 0; na < 4; ++na) {
            const int c0 = (wn + na * 8 + g) * STR + 2 * tg;
            bh[na][0] = *(const u32*)(Bbh + c0);
            bh[na][1] = *(const u32*)(Bbh + c0 + 8);
            bl[na][0] = *(const u32*)(Bbl + c0);
            bl[na][1] = *(const u32*)(Bbl + c0 + 8);
        }

#pragma unroll
        for (int ma = 0; ma < 4; ++ma)
#pragma unroll
            for (int na = 0; na < 4; ++na)
                mma16816(acc[ma][na], ah[ma], bh[na]);
#pragma unroll
        for (int ma = 0; ma < 4; ++ma)
#pragma unroll
            for (int na = 0; na < 4; ++na)
                mma16816(acc[ma][na], ah[ma], bl[na]);
#pragma unroll
        for (int ma = 0; ma < 4; ++ma)
#pragma unroll
            for (int na = 0; na < 4; ++na)
                mma16816(acc[ma][na], al[ma], bh[na]);
        __syncthreads();
    }

#pragma unroll
    for (int ma = 0; ma < 4; ++ma) {
#pragma unroll
        for (int na = 0; na < 4; ++na) {
            const int r0 = bm + wm + ma * 16 + g;
            const int c = bn + wn + na * 8 + 2 * tg;
            *(float2*)(C + (size_t)r0 * Nd + c) =
                make_float2(acc[ma][na][0] * alpha, acc[ma][na][1] * alpha);
            *(float2*)(C + (size_t)(r0 + 8) * Nd + c) =
                make_float2(acc[ma][na][2] * alpha, acc[ma][na][3] * alpha);
        }
    }
}

// ---------------------------------------------------------------------------
// relq[bh,i,r] = q[bh,i,:] . rel_k_table[r,:]   (unchanged)
// ---------------------------------------------------------------------------
__global__ __launch_bounds__(256) void relq_kernel(const float* __restrict__ relk) {
    __shared__ __align__(16) float qsT[64][36];
    __shared__ __align__(16) float tsT[64][132];

    const int tid = threadIdx.x;
    const int bh = blockIdx.y;
    const int b = bh >> 4;
    const int h = bh & 15;
    const int i0 = blockIdx.x * 32;
    const int tx = tid & 31;
    const int ty = tid >> 5;

    {
        const int rI = tid >> 3;
        const int seg = (tid & 7) * 8;
        const float* qb = g_q + (size_t)(b * L + i0 + rI) * D + h * DH + seg;
        float4 v0 = *(const float4*)qb;
        float4 v1 = *(const float4*)(qb + 4);
        qsT[seg + 0][rI] = v0.x; qsT[seg + 1][rI] = v0.y;
        qsT[seg + 2][rI] = v0.z; qsT[seg + 3][rI] = v0.w;
        qsT[seg + 4][rI] = v1.x; qsT[seg + 5][rI] = v1.y;
        qsT[seg + 6][rI] = v1.z; qsT[seg + 7][rI] = v1.w;
    }
    for (int e = tid; e < R * 64; e += 256) {
        int r = e >> 6, d = e & 63;
        tsT[d][r] = relk[e];
    }
    __syncthreads();

    u64 acc2[2][4];
#pragma unroll
    for (int p = 0; p < 2; ++p)
#pragma unroll
        for (int j = 0; j < 4; ++j) acc2[p][j] = 0ull;

#pragma unroll 8
    for (int d = 0; d < 64; ++d) {
        const u64* ap = (const u64*)&qsT[d][ty * 4];
        u64 pa0 = ap[0], pa1 = ap[1];
        float4 bv = *(const float4*)&tsT[d][tx * 4];
        u64 pb0 = dup2(bv.x), pb1 = dup2(bv.y), pb2 = dup2(bv.z), pb3 = dup2(bv.w);
        acc2[0][0] = ffma2(pa0, pb0, acc2[0][0]);
        acc2[0][1] = ffma2(pa0, pb1, acc2[0][1]);
        acc2[0][2] = ffma2(pa0, pb2, acc2[0][2]);
        acc2[0][3] = ffma2(pa0, pb3, acc2[0][3]);
        acc2[1][0] = ffma2(pa1, pb0, acc2[1][0]);
        acc2[1][1] = ffma2(pa1, pb1, acc2[1][1]);
        acc2[1][2] = ffma2(pa1, pb2, acc2[1][2]);
        acc2[1][3] = ffma2(pa1, pb3, acc2[1][3]);
    }

#pragma unroll
    for (int p = 0; p < 2; ++p) {
        float2 c0 = up2(acc2[p][0]);
        float2 c1 = up2(acc2[p][1]);
        float2 c2 = up2(acc2[p][2]);
        float2 c3 = up2(acc2[p][3]);
        int gi = i0 + ty * 4 + 2 * p;
        float* o0 = g_relq + ((size_t)bh * L + gi) * RP + tx * 4;
        float* o1 = o0 + RP;
        *(float4*)o0 = make_float4(c0.x, c1.x, c2.x, c3.x);
        *(float4*)o1 = make_float4(c0.y, c1.y, c2.y, c3.y);
    }

    if (tid < 32) {
        float s = 0.0f;
#pragma unroll 8
        for (int d = 0; d < 64; ++d) s += qsT[d][tid] * tsT[d][128];
        g_relq[((size_t)bh * L + i0 + tid) * RP + 128] = s;
    }
}

// ---------------------------------------------------------------------------
// MEGA-fused attention: logits + softmax + wsum + A@V + rel_v epilogue
// per CTA: (bh, 32 i-rows). grid (L/32=32, BH=32), 256 threads, ~188KB smem.
// Score rows (raw exp) never leave smem; O written directly to g_o.
// ---------------------------------------------------------------------------
namespace {
constexpr int SBS = 1032;  // Sb row stride (floats)
constexpr u32 FUSED_SMEM_FLOATS = 32 * SBS      // Sb (raw logits -> raw exp)
                                  + 64 * 132    // KV  (KsT / VsT / relvT)
                                  + 64 * 36     // QsT
                                  + 32 * 132    // biasW (bias, then raw wsum)
                                  + 32;         // invS
constexpr u32 FUSED_SMEM = FUSED_SMEM_FLOATS * 4;  // 192,128 B
}

__global__ __launch_bounds__(256, 1) void mega_attn_kernel(
        const float* __restrict__ relv) {
    extern __shared__ float fs[];
    float* Sb    = fs;                       // [32][SBS]
    float* KV    = Sb + 32 * SBS;            // [64][132] transposed stage
    float* QsT   = KV + 64 * 132;            // [64][36]
    float* biasW = QsT + 64 * 36;            // [32][132] bias, then wsum(raw)
    float* invS  = biasW + 32 * 132;         // [32]

    const int tid = threadIdx.x;
    const int bh = blockIdx.y;
    const int b = bh >> 4;
    const int h = bh & 15;
    const int i0 = blockIdx.x * 32;

    // ---- stage QsT (32 rows x 64 d, transposed) ----
    {
        const int rI = tid >> 3;            // 0..31
        const int seg = (tid & 7) * 8;      // 0..56
        const float* qb = g_q + (size_t)(b * L + i0 + rI) * D + h * DH + seg;
        float4 v0 = *(const float4*)qb;
        float4 v1 = *(const float4*)(qb + 4);
        QsT[(seg + 0) * 36 + rI] = v0.x; QsT[(seg + 1) * 36 + rI] = v0.y;
        QsT[(seg + 2) * 36 + rI] = v0.z; QsT[(seg + 3) * 36 + rI] = v0.w;
        QsT[(seg + 4) * 36 + rI] = v1.x; QsT[(seg + 5) * 36 + rI] = v1.y;
        QsT[(seg + 6) * 36 + rI] = v1.z; QsT[(seg + 7) * 36 + rI] = v1.w;
    }
    // ---- stage bias rows ----
    for (int e = tid; e < 32 * 132; e += 256) {
        int il = e / 132, r = e - il * 132;
        biasW[e] = (r < R) ? g_relq[((size_t)bh * L + i0 + il) * RP + r] : 0.0f;
    }

    const int ty = tid >> 5;            // 0..7  -> 4 i rows
    const int tx = tid & 31;            // 0..31
    const int rJ = tid >> 1;            // 0..127 (staging row within chunk)
    const int segk = (tid & 1) * 32;    // 0 or 32
    const float* kbase = g_k + (size_t)(b * L + rJ) * D + h * DH + segk;
    const float* vbase = g_v + (size_t)(b * L + rJ) * D + h * DH + segk;

    float4 kreg[8];
#pragma unroll
    for (int u = 0; u < 8; ++u) kreg[u] = *(const float4*)(kbase + 4 * u);
    __syncthreads();   // QsT/biasW staged

    // ============ PHASE 1: logits -> Sb (raw logit + bias) ============
    for (int jc = 0; jc < 8; ++jc) {
#pragma unroll
        for (int u = 0; u < 8; ++u) {
            int c = segk + 4 * u;
            KV[(c + 0) * 132 + rJ] = kreg[u].x;
            KV[(c + 1) * 132 + rJ] = kreg[u].y;
            KV[(c + 2) * 132 + rJ] = kreg[u].z;
            KV[(c + 3) * 132 + rJ] = kreg[u].w;
        }
        __syncthreads();
        if (jc < 7) {
            const float* kb = kbase + (size_t)(jc + 1) * 128 * D;
#pragma unroll
            for (int u = 0; u < 8; ++u) kreg[u] = *(const float4*)(kb + 4 * u);
        }

        u64 acc2[2][4];
#pragma unroll
        for (int p = 0; p < 2; ++p)
#pragma unroll
            for (int j = 0; j < 4; ++j) acc2[p][j] = 0ull;

#pragma unroll 8
        for (int d = 0; d < 64; ++d) {
            const u64* ap = (const u64*)&QsT[d * 36 + ty * 4];
            u64 pa0 = ap[0], pa1 = ap[1];
            float4 bv = *(const float4*)&KV[d * 132 + tx * 4];
            u64 pb0 = dup2(bv.x), pb1 = dup2(bv.y);
            u64 pb2 = dup2(bv.z), pb3 = dup2(bv.w);
            acc2[0][0] = ffma2(pa0, pb0, acc2[0][0]);
            acc2[0][1] = ffma2(pa0, pb1, acc2[0][1]);
            acc2[0][2] = ffma2(pa0, pb2, acc2[0][2]);
            acc2[0][3] = ffma2(pa0, pb3, acc2[0][3]);
            acc2[1][0] = ffma2(pa1, pb0, acc2[1][0]);
            acc2[1][1] = ffma2(pa1, pb1, acc2[1][1]);
            acc2[1][2] = ffma2(pa1, pb2, acc2[1][2]);
            acc2[1][3] = ffma2(pa1, pb3, acc2[1][3]);
        }

        const int jb = jc * 128 + tx * 4;
#pragma unroll
        for (int p = 0; p < 2; ++p) {
            float2 c0 = up2(acc2[p][0]);
            float2 c1 = up2(acc2[p][1]);
            float2 c2 = up2(acc2[p][2]);
            float2 c3 = up2(acc2[p][3]);
#pragma unroll
            for (int e = 0; e < 2; ++e) {
                const int il = ty * 4 + 2 * p + e;
                const int gi = i0 + il;
                const float* brow = biasW + il * 132;
                int r0 = min(max(jb + 0 - gi, -MREL), MREL) + MREL;
                int r1 = min(max(jb + 1 - gi, -MREL), MREL) + MREL;
                int r2 = min(max(jb + 2 - gi, -MREL), MREL) + MREL;
                int r3 = min(max(jb + 3 - gi, -MREL), MREL) + MREL;
                float4 o;
                o.x = (e ? c0.y : c0.x) + brow[r0];
                o.y = (e ? c1.y : c1.x) + brow[r1];
                o.z = (e ? c2.y : c2.x) + brow[r2];
                o.w = (e ? c3.y : c3.x) + brow[r3];
                *(float4*)&Sb[il * SBS + jb] = o;
            }
        }
        __syncthreads();
    }

    // ============ PHASE 2: softmax (raw exp left in Sb) + raw wsum ======
    {
        const int row = tid >> 3;     // 0..31
        const int ts = tid & 7;
        const int gi = i0 + row;
        float* srow = Sb + row * SBS;

        float m = -3.0e38f;
#pragma unroll 8
        for (int c = 0; c < 32; ++c) {
            float4 v = *(const float4*)&srow[ts * 4 + c * 32];
            m = fmaxf(m, fmaxf(fmaxf(v.x, v.y), fmaxf(v.z, v.w)));
        }
#pragma unroll
        for (int o = 4; o > 0; o >>= 1)
            m = fmaxf(m, __shfl_xor_sync(0xffffffffu, m, o));

        float s = 0.0f;
#pragma unroll 8
        for (int c = 0; c < 32; ++c) {
            float4 v = *(float4*)&srow[ts * 4 + c * 32];
            v.x = __expf(v.x - m); v.y = __expf(v.y - m);
            v.z = __expf(v.z - m); v.w = __expf(v.w - m);
            *(float4*)&srow[ts * 4 + c * 32] = v;
            s += v.x + v.y + v.z + v.w;
        }
#pragma unroll
        for (int o = 4; o > 0; o >>= 1) s += __shfl_xor_sync(0xffffffffu, s, o);
        if (ts == 0) invS[row] = 1.0f / s;

        // head / tail partial sums (raw)
        float hp = 0.0f, tp = 0.0f;
        for (int j = ts; j <= gi - MREL; j += 8) hp += srow[j];
        for (int j = gi + MREL + ts; j < L; j += 8) tp += srow[j];
#pragma unroll
        for (int o = 4; o > 0; o >>= 1) {
            hp += __shfl_xor_sync(0xffffffffu, hp, o);
            tp += __shfl_xor_sync(0xffffffffu, tp, o);
        }
        __syncthreads();   // all exp writes done; biasW free for reuse

        // raw wsum into biasW[row][r]
        float* wrow = biasW + row * 132;
#pragma unroll
        for (int k = 0; k < 16; ++k) {
            int r = 1 + ts * 16 + k;
            if (r < 128) {
                int j = gi + r - 64;
                wrow[r] = (j >= 0 && j < L) ? srow[j] : 0.0f;
            }
        }
        if (ts == 0) {
            wrow[0] = hp;
            wrow[128] = tp;
        }
    }

    // ============ PHASE 3: O = exp @ V (acc paired over j) ============
    u64 vacc[4][2];
#pragma unroll
    for (int i = 0; i < 4; ++i) { vacc[i][0] = 0ull; vacc[i][1] = 0ull; }

    const float* wr0 = Sb + (ty * 4 + 0) * SBS;
    const float* wr1 = Sb + (ty * 4 + 1) * SBS;
    const float* wr2 = Sb + (ty * 4 + 2) * SBS;
    const float* wr3 = Sb + (ty * 4 + 3) * SBS;
    const int d0 = tx * 2, d1 = tx * 2 + 1;

    float4 vreg[8];
#pragma unroll
    for (int u = 0; u < 8; ++u) vreg[u] = *(const float4*)(vbase + 4 * u);
    __syncthreads();   // wsum writes done; KV free for V staging

    for (int jc = 0; jc < 8; ++jc) {
#pragma unroll
        for (int u = 0; u < 8; ++u) {
            int c = segk + 4 * u;
            KV[(c + 0) * 132 + rJ] = vreg[u].x;
            KV[(c + 1) * 132 + rJ] = vreg[u].y;
            KV[(c + 2) * 132 + rJ] = vreg[u].z;
            KV[(c + 3) * 132 + rJ] = vreg[u].w;
        }
        __syncthreads();
        if (jc < 7) {
            const float* vb = vbase + (size_t)(jc + 1) * 128 * D;
#pragma unroll
            for (int u = 0; u < 8; ++u) vreg[u] = *(const float4*)(vb + 4 * u);
        }

        const int jbase = jc * 128;
        const float* vp0 = KV + d0 * 132;
        const float* vp1 = KV + d1 * 132;
#pragma unroll 4
        for (int jq = 0; jq < 128; jq += 4) {
            const int j = jbase + jq;
            u64 va0 = *(const u64*)(vp0 + jq);
            u64 va1 = *(const u64*)(vp0 + jq + 2);
            u64 vb0 = *(const u64*)(vp1 + jq);
            u64 vb1 = *(const u64*)(vp1 + jq + 2);
            u64 w0a = *(const u64*)(wr0 + j), w0b = *(const u64*)(wr0 + j + 2);
            u64 w1a = *(const u64*)(wr1 + j), w1b = *(const u64*)(wr1 + j + 2);
            u64 w2a = *(const u64*)(wr2 + j), w2b = *(const u64*)(wr2 + j + 2);
            u64 w3a = *(const u64*)(wr3 + j), w3b = *(const u64*)(wr3 + j + 2);
            vacc[0][0] = ffma2(w0a, va0, vacc[0][0]);
            vacc[0][0] = ffma2(w0b, va1, vacc[0][0]);
            vacc[0][1] = ffma2(w0a, vb0, vacc[0][1]);
            vacc[0][1] = ffma2(w0b, vb1, vacc[0][1]);
            vacc[1][0] = ffma2(w1a, va0, vacc[1][0]);
            vacc[1][0] = ffma2(w1b, va1, vacc[1][0]);
            vacc[1][1] = ffma2(w1a, vb0, vacc[1][1]);
            vacc[1][1] = ffma2(w1b, vb1, vacc[1][1]);
            vacc[2][0] = ffma2(w2a, va0, vacc[2][0]);
            vacc[2][0] = ffma2(w2b, va1, vacc[2][0]);
            vacc[2][1] = ffma2(w2a, vb0, vacc[2][1]);
            vacc[2][1] = ffma2(w2b, vb1, vacc[2][1]);
            vacc[3][0] = ffma2(w3a, va0, vacc[3][0]);
            vacc[3][0] = ffma2(w3b, va1, vacc[3][0]);
            vacc[3][1] = ffma2(w3a, vb0, vacc[3][1]);
            vacc[3][1] = ffma2(w3b, vb1, vacc[3][1]);
        }
        __syncthreads();
    }

    // ============ PHASE 4: rel_v epilogue (acc paired over r) ============
    // stage relvT[d][r] into KV
    for (int e = tid; e < R * 64; e += 256) {
        int r = e >> 6, d = e & 63;
        KV[d * 132 + r] = relv[e];
    }
    __syncthreads();

    {
        const float* u0 = biasW + (ty * 4 + 0) * 132;
        const float* u1 = biasW + (ty * 4 + 1) * 132;
        const float* u2 = biasW + (ty * 4 + 2) * 132;
        const float* u3 = biasW + (ty * 4 + 3) * 132;
        const float* vp0 = KV + d0 * 132;
        const float* vp1 = KV + d1 * 132;
#pragma unroll 4
        for (int rq = 0; rq < 128; rq += 4) {
            u64 va0 = *(const u64*)(vp0 + rq);
            u64 va1 = *(const u64*)(vp0 + rq + 2);
            u64 vb0 = *(const u64*)(vp1 + rq);
            u64 vb1 = *(const u64*)(vp1 + rq + 2);
            u64 w0a = *(const u64*)(u0 + rq), w0b = *(const u64*)(u0 + rq + 2);
            u64 w1a = *(const u64*)(u1 + rq), w1b = *(const u64*)(u1 + rq + 2);
            u64 w2a = *(const u64*)(u2 + rq), w2b = *(const u64*)(u2 + rq + 2);
            u64 w3a = *(const u64*)(u3 + rq), w3b = *(const u64*)(u3 + rq + 2);
            vacc[0][0] = ffma2(w0a, va0, vacc[0][0]);
            vacc[0][0] = ffma2(w0b, va1, vacc[0][0]);
            vacc[0][1] = ffma2(w0a, vb0, vacc[0][1]);
            vacc[0][1] = ffma2(w0b, vb1, vacc[0][1]);
            vacc[1][0] = ffma2(w1a, va0, vacc[1][0]);
            vacc[1][0] = ffma2(w1b, va1, vacc[1][0]);
            vacc[1][1] = ffma2(w1a, vb0, vacc[1][1]);
            vacc[1][1] = ffma2(w1b, vb1, vacc[1][1]);
            vacc[2][0] = ffma2(w2a, va0, vacc[2][0]);
            vacc[2][0] = ffma2(w2b, va1, vacc[2][0]);
            vacc[2][1] = ffma2(w2a, vb0, vacc[2][1]);
            vacc[2][1] = ffma2(w2b, vb1, vacc[2][1]);
            vacc[3][0] = ffma2(w3a, va0, vacc[3][0]);
            vacc[3][0] = ffma2(w3b, va1, vacc[3][0]);
            vacc[3][1] = ffma2(w3a, vb0, vacc[3][1]);
            vacc[3][1] = ffma2(w3b, vb1, vacc[3][1]);
        }
    }

    // ---- writeout: unpack, add r=128 tail term, scale by 1/sum ----
#pragma unroll
    for (int i = 0; i < 4; ++i) {
        const int il = ty * 4 + i;
        const int gi = i0 + il;
        const float wt = biasW[il * 132 + 128];   // raw tail wsum
        const float iv = invS[il];
        float2 sa = up2(vacc[i][0]);
        float2 sb = up2(vacc[i][1]);
        float o0 = (sa.x + sa.y + wt * KV[d0 * 132 + 128]) * iv;
        float o1 = (sb.x + sb.y + wt * KV[d1 * 132 + 128]) * iv;
        *(float2*)(g_o + (size_t)(b * L + gi) * D + h * DH + d0) =
            make_float2(o0, o1);
    }
}

// ---------------------------------------------------------------------------
// Launch
// ---------------------------------------------------------------------------
extern "C" void kernel_launch(void* const* d_in, const int* in_sizes, int n_in,
                              void* d_out, int out_size) {
    const float* x    = (const float*)d_in[0];
    const float* Wq   = (const float*)d_in[1];
    const float* Wk   = (const float*)d_in[2];
    const float* Wv   = (const float*)d_in[3];
    const float* Wo   = (const float*)d_in[4];
    const float* relk = (const float*)d_in[5];
    const float* relv = (const float*)d_in[6];
    float* out = (float*)d_out;

    float *pq, *pk, *pv, *po;
    cudaGetSymbolAddress((void**)&pq, g_q);
    cudaGetSymbolAddress((void**)&pk, g_k);
    cudaGetSymbolAddress((void**)&pv, g_v);
    cudaGetSymbolAddress((void**)&po, g_o);
    bf16 *xh, *xl, *wh, *wl;
    cudaGetSymbolAddress((void**)&xh, g_xh);
    cudaGetSymbolAddress((void**)&xl, g_xl);
    cudaGetSymbolAddress((void**)&wh, g_wh);
    cudaGetSymbolAddress((void**)&wl, g_wl);

    cudaFuncSetAttribute(mega_attn_kernel,
                         cudaFuncAttributeMaxDynamicSharedMemorySize,
                         (int)FUSED_SMEM);

    const dim3 gg(D / 128, NT / 128);       // (8, 16) = 128 CTAs
    const dim3 gt(32, 32);
    const dim3 bt(32, 8);
    const int splitBlocks = (NT * D) / (256 * 4);   // 2048
    const float qscale = 0.125f;            // DH^-0.5

    // x split once, reused for q/k/v
    split_kernel<<<splitBlocks, 256>>>(x, xh, xl);

    splitT_kernel<<<gt, bt>>>(Wq, wh, wl);
    hgemm3x<<<gg, 256>>>(xh, xl, wh, wl, pq, NT, D, D, qscale);

    splitT_kernel<<<gt, bt>>>(Wk, wh, wl);
    hgemm3x<<<gg, 256>>>(xh, xl, wh, wl, pk, NT, D, D, 1.0f);

    splitT_kernel<<<gt, bt>>>(Wv, wh, wl);
    hgemm3x<<<gg, 256>>>(xh, xl, wh, wl, pv, NT, D, D, 1.0f);

    relq_kernel<<<dim3(L / 32, BH), 256>>>(relk);

    // fully fused attention: logits + softmax + wsum + A@V + rel_v
    mega_attn_kernel<<<dim3(L / 32, BH), 256, FUSED_SMEM>>>(relv);

    // final projection
    split_kernel<<<splitBlocks, 256>>>(po, xh, xl);
    splitT_kernel<<<gt, bt>>>(Wo, wh, wl);
    hgemm3x<<<gg, 256>>>(xh, xl, wh, wl, out, NT, D, D, 1.0f);
}

// round 11
// speedup vs baseline: 1.0659x; 1.0659x over previous
#include <cuda_runtime.h>
#include <cuda_bf16.h>
#include <cstdint>

// ---------------------------------------------------------------------------
// MultiHead2DAttention (Shaw relative positions, T2T variant)
// B=2, L=1024, D=1024, H=16, DH=64, M=64, R=129
// Round 10: mega-fused attention with CORRECT conflict fix.
//   Phase 1 (K): stride 132, float4 loads (aligned, conflict-free — as R7/R8)
//   Phase 3/4 (V/relv): stride 130, d0=tx / d1=tx+32 u64 loads
//     -> 8-byte aligned (130*tx always even) AND bank-conflict-free
//        (130 = 2 mod 32 -> lanes hit disjoint bank pairs).
// R9's odd stride (133) caused the misaligned-address trap.
// ---------------------------------------------------------------------------

namespace {
constexpr int B  = 2;
constexpr int L  = 1024;
constexpr int D  = 1024;
constexpr int H  = 16;
constexpr int DH = 64;
constexpr int MREL = 64;
constexpr int R  = 2 * MREL + 1;   // 129
constexpr int RP = 132;            // padded row stride for relq
constexpr int NT = B * L;          // 2048
constexpr int BH = B * H;          // 32
constexpr int KST = 132;           // K-stage stride (phase 1, float4 access)
constexpr int VST = 130;           // V-stage stride (phase 3/4, u64 access)
}

typedef __nv_bfloat16 bf16;
typedef unsigned long long u64;
typedef unsigned int u32;

// Scratch buffers (device globals: no allocations allowed)
__device__ float g_q[NT * D];
__device__ float g_k[NT * D];
__device__ float g_v[NT * D];
__device__ float g_o[NT * D];
__device__ float g_relq[(size_t)BH * L * RP];

// bf16 split buffers
__device__ bf16 g_xh[NT * D];
__device__ bf16 g_xl[NT * D];
__device__ bf16 g_wh[D * D];     // transposed [N][K]
__device__ bf16 g_wl[D * D];

// ---------------------------------------------------------------------------
// packed fp32 helpers
// ---------------------------------------------------------------------------
__device__ __forceinline__ u64 pk2(float x, float y) {
    u64 r;
    asm("mov.b64 %0, {%1, %2};" : "=l"(r) : "f"(x), "f"(y));
    return r;
}
__device__ __forceinline__ u64 dup2(float x) { return pk2(x, x); }
__device__ __forceinline__ u64 ffma2(u64 a, u64 b, u64 c) {
    u64 d;
    asm("fma.rn.f32x2 %0, %1, %2, %3;" : "=l"(d) : "l"(a), "l"(b), "l"(c));
    return d;
}
__device__ __forceinline__ float2 up2(u64 v) {
    float2 f;
    asm("mov.b64 {%0, %1}, %2;" : "=f"(f.x), "=f"(f.y) : "l"(v));
    return f;
}

// ---------------------------------------------------------------------------
// mma helper: D(f32) += A(bf16 16x16) * B(bf16 16x8)
// ---------------------------------------------------------------------------
__device__ __forceinline__ void mma16816(float* c, const u32* a, const u32* b) {
    asm volatile(
        "mma.sync.aligned.m16n8k16.row.col.f32.bf16.bf16.f32 "
        "{%0,%1,%2,%3},{%4,%5,%6,%7},{%8,%9},{%0,%1,%2,%3};"
        : "+f"(c[0]), "+f"(c[1]), "+f"(c[2]), "+f"(c[3])
        : "r"(a[0]), "r"(a[1]), "r"(a[2]), "r"(a[3]), "r"(b[0]), "r"(b[1]));
}

__device__ __forceinline__ void cp16(u32 smem_addr, const void* gptr) {
    asm volatile("cp.async.cg.shared.global [%0], [%1], 16;"
                 :: "r"(smem_addr), "l"(gptr));
}

// ---------------------------------------------------------------------------
// split: src fp32 -> hi/lo bf16 (elementwise)
// ---------------------------------------------------------------------------
__global__ __launch_bounds__(256) void split_kernel(const float* __restrict__ src,
                                                    bf16* __restrict__ hi,
                                                    bf16* __restrict__ lo) {
    int i = (blockIdx.x * 256 + threadIdx.x) * 4;
    float4 v = *(const float4*)(src + i);
    bf16 h0 = __float2bfloat16(v.x);
    bf16 h1 = __float2bfloat16(v.y);
    bf16 h2 = __float2bfloat16(v.z);
    bf16 h3 = __float2bfloat16(v.w);
    bf16 l0 = __float2bfloat16(v.x - __bfloat162float(h0));
    bf16 l1 = __float2bfloat16(v.y - __bfloat162float(h1));
    bf16 l2 = __float2bfloat16(v.z - __bfloat162float(h2));
    bf16 l3 = __float2bfloat16(v.w - __bfloat162float(h3));
    __nv_bfloat162* hp = (__nv_bfloat162*)(hi + i);
    __nv_bfloat162* lp = (__nv_bfloat162*)(lo + i);
    hp[0] = __nv_bfloat162(h0, h1);
    hp[1] = __nv_bfloat162(h2, h3);
    lp[0] = __nv_bfloat162(l0, l1);
    lp[1] = __nv_bfloat162(l2, l3);
}

// ---------------------------------------------------------------------------
// splitT: W[K][N] fp32 -> transposed hi/lo bf16 [N][K]
// ---------------------------------------------------------------------------
__global__ void splitT_kernel(const float* __restrict__ W,
                              bf16* __restrict__ th, bf16* __restrict__ tl) {
    __shared__ float ts[32][33];
    const int tx = threadIdx.x, ty = threadIdx.y;
    const int n0 = blockIdx.x * 32, k0 = blockIdx.y * 32;
    for (int r = ty; r < 32; r += 8)
        ts[r][tx] = W[(size_t)(k0 + r) * D + n0 + tx];
    __syncthreads();
    for (int r = ty; r < 32; r += 8) {
        float v = ts[tx][r];
        bf16 h = __float2bfloat16(v);
        bf16 l = __float2bfloat16(v - __bfloat162float(h));
        th[(size_t)(n0 + r) * D + k0 + tx] = h;
        tl[(size_t)(n0 + r) * D + k0 + tx] = l;
    }
}

// ---------------------------------------------------------------------------
// hgemm3x: C[M,N] = alpha * A[M,K] @ B[K,N]  (unchanged, known-good)
// ---------------------------------------------------------------------------
__global__ __launch_bounds__(256) void hgemm3x(const bf16* __restrict__ Ah,
                                               const bf16* __restrict__ Al,
                                               const bf16* __restrict__ Bh,
                                               const bf16* __restrict__ Bl,
                                               float* __restrict__ C,
                                               int Md, int Nd, int Kd,
                                               float alpha) {
    constexpr int STR = 24;
    constexpr int STG = 128 * STR;
    __shared__ bf16 As_h[2 * STG];
    __shared__ bf16 As_l[2 * STG];
    __shared__ bf16 Bs_h[2 * STG];
    __shared__ bf16 Bs_l[2 * STG];

    const int tid = threadIdx.x;
    const int bm = blockIdx.y * 128;
    const int bn = blockIdx.x * 128;
    const int wid = tid >> 5;
    const int lane = tid & 31;
    const int g = lane >> 2;
    const int tg = lane & 3;
    const int wm = (wid & 1) * 64;
    const int wn = (wid >> 1) * 32;

    const int lrow = tid >> 1;
    const int lseg = (tid & 1) * 8;
    const size_t aoff = (size_t)(bm + lrow) * Kd + lseg;
    const size_t boff = (size_t)(bn + lrow) * Kd + lseg;
    const u32 sdst = (u32)(lrow * STR + lseg) * 2;
    const u32 s_ah = (u32)__cvta_generic_to_shared(As_h);
    const u32 s_al = (u32)__cvta_generic_to_shared(As_l);
    const u32 s_bh = (u32)__cvta_generic_to_shared(Bs_h);
    const u32 s_bl = (u32)__cvta_generic_to_shared(Bs_l);

    float acc[4][4][4];
#pragma unroll
    for (int ma = 0; ma < 4; ++ma)
#pragma unroll
        for (int na = 0; na < 4; ++na)
#pragma unroll
            for (int e = 0; e < 4; ++e) acc[ma][na][e] = 0.0f;

    const int nT = Kd / 16;

    {
        const u32 o = sdst;
        cp16(s_ah + o, Ah + aoff);
        cp16(s_al + o, Al + aoff);
        cp16(s_bh + o, Bh + boff);
        cp16(s_bl + o, Bl + boff);
        asm volatile("cp.async.commit_group;");
    }

    for (int kt = 0; kt < nT; ++kt) {
        const int stg = kt & 1;
        if (kt + 1 < nT) {
            const u32 o = (u32)((stg ^ 1) * STG * 2) + sdst;
            const size_t ko = (size_t)(kt + 1) * 16;
            cp16(s_ah + o, Ah + aoff + ko);
            cp16(s_al + o, Al + aoff + ko);
            cp16(s_bh + o, Bh + boff + ko);
            cp16(s_bl + o, Bl + boff + ko);
            asm volatile("cp.async.commit_group;");
            asm volatile("cp.async.wait_group 1;");
        } else {
            asm volatile("cp.async.wait_group 0;");
        }
        __syncthreads();

        const bf16* Abh = As_h + stg * STG;
        const bf16* Abl = As_l + stg * STG;
        const bf16* Bbh = Bs_h + stg * STG;
        const bf16* Bbl = Bs_l + stg * STG;

        u32 ah[4][4], al[4][4], bh[4][2], bl[4][2];
#pragma unroll
        for (int ma = 0; ma < 4; ++ma) {
            const int r0 = (wm + ma * 16 + g) * STR + 2 * tg;
            const int r1 = r0 + 8 * STR;
            ah[ma][0] = *(const u32*)(Abh + r0);
            ah[ma][1] = *(const u32*)(Abh + r1);
            ah[ma][2] = *(const u32*)(Abh + r0 + 8);
            ah[ma][3] = *(const u32*)(Abh + r1 + 8);
            al[ma][0] = *(const u32*)(Abl + r0);
            al[ma][1] = *(const u32*)(Abl + r1);
            al[ma][2] = *(const u32*)(Abl + r0 + 8);
            al[ma][3] = *(const u32*)(Abl + r1 + 8);
        }
#pragma unroll
        for (int na = 0; na < 4; ++na) {
            const int c0 = (wn + na * 8 + g) * STR + 2 * tg;
            bh[na][0] = *(const u32*)(Bbh + c0);
            bh[na][1] = *(const u32*)(Bbh + c0 + 8);
            bl[na][0] = *(const u32*)(Bbl + c0);
            bl[na][1] = *(const u32*)(Bbl + c0 + 8);
        }

#pragma unroll
        for (int ma = 0; ma < 4; ++ma)
#pragma unroll
            for (int na = 0; na < 4; ++na)
                mma16816(acc[ma][na], ah[ma], bh[na]);
#pragma unroll
        for (int ma = 0; ma < 4; ++ma)
#pragma unroll
            for (int na = 0; na < 4; ++na)
                mma16816(acc[ma][na], ah[ma], bl[na]);
#pragma unroll
        for (int ma = 0; ma < 4; ++ma)
#pragma unroll
            for (int na = 0; na < 4; ++na)
                mma16816(acc[ma][na], al[ma], bh[na]);
        __syncthreads();
    }

#pragma unroll
    for (int ma = 0; ma < 4; ++ma) {
#pragma unroll
        for (int na = 0; na < 4; ++na) {
            const int r0 = bm + wm + ma * 16 + g;
            const int c = bn + wn + na * 8 + 2 * tg;
            *(float2*)(C + (size_t)r0 * Nd + c) =
                make_float2(acc[ma][na][0] * alpha, acc[ma][na][1] * alpha);
            *(float2*)(C + (size_t)(r0 + 8) * Nd + c) =
                make_float2(acc[ma][na][2] * alpha, acc[ma][na][3] * alpha);
        }
    }
}

// ---------------------------------------------------------------------------
// relq[bh,i,r] = q[bh,i,:] . rel_k_table[r,:]   (unchanged)
// ---------------------------------------------------------------------------
__global__ __launch_bounds__(256) void relq_kernel(const float* __restrict__ relk) {
    __shared__ __align__(16) float qsT[64][36];
    __shared__ __align__(16) float tsT[64][132];

    const int tid = threadIdx.x;
    const int bh = blockIdx.y;
    const int b = bh >> 4;
    const int h = bh & 15;
    const int i0 = blockIdx.x * 32;
    const int tx = tid & 31;
    const int ty = tid >> 5;

    {
        const int rI = tid >> 3;
        const int seg = (tid & 7) * 8;
        const float* qb = g_q + (size_t)(b * L + i0 + rI) * D + h * DH + seg;
        float4 v0 = *(const float4*)qb;
        float4 v1 = *(const float4*)(qb + 4);
        qsT[seg + 0][rI] = v0.x; qsT[seg + 1][rI] = v0.y;
        qsT[seg + 2][rI] = v0.z; qsT[seg + 3][rI] = v0.w;
        qsT[seg + 4][rI] = v1.x; qsT[seg + 5][rI] = v1.y;
        qsT[seg + 6][rI] = v1.z; qsT[seg + 7][rI] = v1.w;
    }
    for (int e = tid; e < R * 64; e += 256) {
        int r = e >> 6, d = e & 63;
        tsT[d][r] = relk[e];
    }
    __syncthreads();

    u64 acc2[2][4];
#pragma unroll
    for (int p = 0; p < 2; ++p)
#pragma unroll
        for (int j = 0; j < 4; ++j) acc2[p][j] = 0ull;

#pragma unroll 8
    for (int d = 0; d < 64; ++d) {
        const u64* ap = (const u64*)&qsT[d][ty * 4];
        u64 pa0 = ap[0], pa1 = ap[1];
        float4 bv = *(const float4*)&tsT[d][tx * 4];
        u64 pb0 = dup2(bv.x), pb1 = dup2(bv.y), pb2 = dup2(bv.z), pb3 = dup2(bv.w);
        acc2[0][0] = ffma2(pa0, pb0, acc2[0][0]);
        acc2[0][1] = ffma2(pa0, pb1, acc2[0][1]);
        acc2[0][2] = ffma2(pa0, pb2, acc2[0][2]);
        acc2[0][3] = ffma2(pa0, pb3, acc2[0][3]);
        acc2[1][0] = ffma2(pa1, pb0, acc2[1][0]);
        acc2[1][1] = ffma2(pa1, pb1, acc2[1][1]);
        acc2[1][2] = ffma2(pa1, pb2, acc2[1][2]);
        acc2[1][3] = ffma2(pa1, pb3, acc2[1][3]);
    }

#pragma unroll
    for (int p = 0; p < 2; ++p) {
        float2 c0 = up2(acc2[p][0]);
        float2 c1 = up2(acc2[p][1]);
        float2 c2 = up2(acc2[p][2]);
        float2 c3 = up2(acc2[p][3]);
        int gi = i0 + ty * 4 + 2 * p;
        float* o0 = g_relq + ((size_t)bh * L + gi) * RP + tx * 4;
        float* o1 = o0 + RP;
        *(float4*)o0 = make_float4(c0.x, c1.x, c2.x, c3.x);
        *(float4*)o1 = make_float4(c0.y, c1.y, c2.y, c3.y);
    }

    if (tid < 32) {
        float s = 0.0f;
#pragma unroll 8
        for (int d = 0; d < 64; ++d) s += qsT[d][tid] * tsT[d][128];
        g_relq[((size_t)bh * L + i0 + tid) * RP + 128] = s;
    }
}

// ---------------------------------------------------------------------------
// MEGA-fused attention: logits + softmax + wsum + A@V + rel_v epilogue
// per CTA: (bh, 32 i-rows). grid (L/32=32, BH=32), 256 threads.
// ---------------------------------------------------------------------------
namespace {
constexpr int SBS = 1032;  // Sb row stride (floats)
constexpr u32 FUSED_SMEM_FLOATS = 32 * SBS       // Sb (raw logits -> raw exp)
                                  + 64 * KST     // KV  (KsT / VsT / relvT)
                                  + 64 * 36      // QsT
                                  + 32 * 132     // biasW (bias, then raw wsum)
                                  + 32;          // invS
constexpr u32 FUSED_SMEM = FUSED_SMEM_FLOATS * 4;
}

__global__ __launch_bounds__(256, 1) void mega_attn_kernel(
        const float* __restrict__ relv) {
    extern __shared__ float fs[];
    float* Sb    = fs;                       // [32][SBS]
    float* KV    = Sb + 32 * SBS;            // [64][KST] (K) / [64][VST] (V)
    float* QsT   = KV + 64 * KST;            // [64][36]
    float* biasW = QsT + 64 * 36;            // [32][132] bias, then wsum(raw)
    float* invS  = biasW + 32 * 132;         // [32]

    const int tid = threadIdx.x;
    const int bh = blockIdx.y;
    const int b = bh >> 4;
    const int h = bh & 15;
    const int i0 = blockIdx.x * 32;

    // ---- stage QsT (32 rows x 64 d, transposed) ----
    {
        const int rI = tid >> 3;            // 0..31
        const int seg = (tid & 7) * 8;      // 0..56
        const float* qb = g_q + (size_t)(b * L + i0 + rI) * D + h * DH + seg;
        float4 v0 = *(const float4*)qb;
        float4 v1 = *(const float4*)(qb + 4);
        QsT[(seg + 0) * 36 + rI] = v0.x; QsT[(seg + 1) * 36 + rI] = v0.y;
        QsT[(seg + 2) * 36 + rI] = v0.z; QsT[(seg + 3) * 36 + rI] = v0.w;
        QsT[(seg + 4) * 36 + rI] = v1.x; QsT[(seg + 5) * 36 + rI] = v1.y;
        QsT[(seg + 6) * 36 + rI] = v1.z; QsT[(seg + 7) * 36 + rI] = v1.w;
    }
    // ---- stage bias rows ----
    for (int e = tid; e < 32 * 132; e += 256) {
        int il = e / 132, r = e - il * 132;
        biasW[e] = (r < R) ? g_relq[((size_t)bh * L + i0 + il) * RP + r] : 0.0f;
    }

    const int ty = tid >> 5;            // 0..7  -> 4 i rows
    const int tx = tid & 31;            // 0..31
    const int rJ = tid >> 1;            // 0..127 (staging row within chunk)
    const int segk = (tid & 1) * 32;    // 0 or 32
    const float* kbase = g_k + (size_t)(b * L + rJ) * D + h * DH + segk;
    const float* vbase = g_v + (size_t)(b * L + rJ) * D + h * DH + segk;

    float4 kreg[8];
#pragma unroll
    for (int u = 0; u < 8; ++u) kreg[u] = *(const float4*)(kbase + 4 * u);
    __syncthreads();   // QsT/biasW staged

    // ============ PHASE 1: logits -> Sb (raw logit + bias) ============
    for (int jc = 0; jc < 8; ++jc) {
#pragma unroll
        for (int u = 0; u < 8; ++u) {
            int c = segk + 4 * u;
            KV[(c + 0) * KST + rJ] = kreg[u].x;
            KV[(c + 1) * KST + rJ] = kreg[u].y;
            KV[(c + 2) * KST + rJ] = kreg[u].z;
            KV[(c + 3) * KST + rJ] = kreg[u].w;
        }
        __syncthreads();
        if (jc < 7) {
            const float* kb = kbase + (size_t)(jc + 1) * 128 * D;
#pragma unroll
            for (int u = 0; u < 8; ++u) kreg[u] = *(const float4*)(kb + 4 * u);
        }

        u64 acc2[2][4];
#pragma unroll
        for (int p = 0; p < 2; ++p)
#pragma unroll
            for (int j = 0; j < 4; ++j) acc2[p][j] = 0ull;

#pragma unroll 8
        for (int d = 0; d < 64; ++d) {
            const u64* ap = (const u64*)&QsT[d * 36 + ty * 4];
            u64 pa0 = ap[0], pa1 = ap[1];
            float4 bv = *(const float4*)&KV[d * KST + tx * 4];
            u64 pb0 = dup2(bv.x), pb1 = dup2(bv.y);
            u64 pb2 = dup2(bv.z), pb3 = dup2(bv.w);
            acc2[0][0] = ffma2(pa0, pb0, acc2[0][0]);
            acc2[0][1] = ffma2(pa0, pb1, acc2[0][1]);
            acc2[0][2] = ffma2(pa0, pb2, acc2[0][2]);
            acc2[0][3] = ffma2(pa0, pb3, acc2[0][3]);
            acc2[1][0] = ffma2(pa1, pb0, acc2[1][0]);
            acc2[1][1] = ffma2(pa1, pb1, acc2[1][1]);
            acc2[1][2] = ffma2(pa1, pb2, acc2[1][2]);
            acc2[1][3] = ffma2(pa1, pb3, acc2[1][3]);
        }

        const int jb = jc * 128 + tx * 4;
#pragma unroll
        for (int p = 0; p < 2; ++p) {
            float2 c0 = up2(acc2[p][0]);
            float2 c1 = up2(acc2[p][1]);
            float2 c2 = up2(acc2[p][2]);
            float2 c3 = up2(acc2[p][3]);
#pragma unroll
            for (int e = 0; e < 2; ++e) {
                const int il = ty * 4 + 2 * p + e;
                const int gi = i0 + il;
                const float* brow = biasW + il * 132;
                int r0 = min(max(jb + 0 - gi, -MREL), MREL) + MREL;
                int r1 = min(max(jb + 1 - gi, -MREL), MREL) + MREL;
                int r2 = min(max(jb + 2 - gi, -MREL), MREL) + MREL;
                int r3 = min(max(jb + 3 - gi, -MREL), MREL) + MREL;
                float4 o;
                o.x = (e ? c0.y : c0.x) + brow[r0];
                o.y = (e ? c1.y : c1.x) + brow[r1];
                o.z = (e ? c2.y : c2.x) + brow[r2];
                o.w = (e ? c3.y : c3.x) + brow[r3];
                *(float4*)&Sb[il * SBS + jb] = o;
            }
        }
        __syncthreads();
    }

    // ============ PHASE 2: softmax (raw exp left in Sb) + raw wsum ======
    {
        const int row = tid >> 3;     // 0..31
        const int ts = tid & 7;
        const int gi = i0 + row;
        float* srow = Sb + row * SBS;

        float m = -3.0e38f;
#pragma unroll 8
        for (int c = 0; c < 32; ++c) {
            float4 v = *(const float4*)&srow[ts * 4 + c * 32];
            m = fmaxf(m, fmaxf(fmaxf(v.x, v.y), fmaxf(v.z, v.w)));
        }
#pragma unroll
        for (int o = 4; o > 0; o >>= 1)
            m = fmaxf(m, __shfl_xor_sync(0xffffffffu, m, o));

        float s = 0.0f;
#pragma unroll 8
        for (int c = 0; c < 32; ++c) {
            float4 v = *(float4*)&srow[ts * 4 + c * 32];
            v.x = __expf(v.x - m); v.y = __expf(v.y - m);
            v.z = __expf(v.z - m); v.w = __expf(v.w - m);
            *(float4*)&srow[ts * 4 + c * 32] = v;
            s += v.x + v.y + v.z + v.w;
        }
#pragma unroll
        for (int o = 4; o > 0; o >>= 1) s += __shfl_xor_sync(0xffffffffu, s, o);
        if (ts == 0) invS[row] = 1.0f / s;

        // head / tail partial sums (raw)
        float hp = 0.0f, tp = 0.0f;
        for (int j = ts; j <= gi - MREL; j += 8) hp += srow[j];
        for (int j = gi + MREL + ts; j < L; j += 8) tp += srow[j];
#pragma unroll
        for (int o = 4; o > 0; o >>= 1) {
            hp += __shfl_xor_sync(0xffffffffu, hp, o);
            tp += __shfl_xor_sync(0xffffffffu, tp, o);
        }
        __syncthreads();   // all exp writes done; biasW free for reuse

        // raw wsum into biasW[row][r]
        float* wrow = biasW + row * 132;
#pragma unroll
        for (int k = 0; k < 16; ++k) {
            int r = 1 + ts * 16 + k;
            if (r < 128) {
                int j = gi + r - 64;
                wrow[r] = (j >= 0 && j < L) ? srow[j] : 0.0f;
            }
        }
        if (ts == 0) {
            wrow[0] = hp;
            wrow[128] = tp;
        }
    }

    // ============ PHASE 3: O = exp @ V (acc paired over j) ============
    // V staged d-major with stride VST=130; thread handles d0=tx, d1=tx+32.
    u64 vacc[4][2];
#pragma unroll
    for (int i = 0; i < 4; ++i) { vacc[i][0] = 0ull; vacc[i][1] = 0ull; }

    const float* wr0 = Sb + (ty * 4 + 0) * SBS;
    const float* wr1 = Sb + (ty * 4 + 1) * SBS;
    const float* wr2 = Sb + (ty * 4 + 2) * SBS;
    const float* wr3 = Sb + (ty * 4 + 3) * SBS;
    const int d0 = tx, d1 = tx + 32;

    float4 vreg[8];
#pragma unroll
    for (int u = 0; u < 8; ++u) vreg[u] = *(const float4*)(vbase + 4 * u);
    __syncthreads();   // wsum writes done; KV free for V staging

    for (int jc = 0; jc < 8; ++jc) {
#pragma unroll
        for (int u = 0; u < 8; ++u) {
            int c = segk + 4 * u;
            KV[(c + 0) * VST + rJ] = vreg[u].x;
            KV[(c + 1) * VST + rJ] = vreg[u].y;
            KV[(c + 2) * VST + rJ] = vreg[u].z;
            KV[(c + 3) * VST + rJ] = vreg[u].w;
        }
        __syncthreads();
        if (jc < 7) {
            const float* vb = vbase + (size_t)(jc + 1) * 128 * D;
#pragma unroll
            for (int u = 0; u < 8; ++u) vreg[u] = *(const float4*)(vb + 4 * u);
        }

        const int jbase = jc * 128;
        const float* vp0 = KV + d0 * VST;
        const float* vp1 = KV + d1 * VST;
#pragma unroll 4
        for (int jq = 0; jq < 128; jq += 4) {
            const int j = jbase + jq;
            u64 va0 = *(const u64*)(vp0 + jq);
            u64 va1 = *(const u64*)(vp0 + jq + 2);
            u64 vb0 = *(const u64*)(vp1 + jq);
            u64 vb1 = *(const u64*)(vp1 + jq + 2);
            u64 w0a = *(const u64*)(wr0 + j), w0b = *(const u64*)(wr0 + j + 2);
            u64 w1a = *(const u64*)(wr1 + j), w1b = *(const u64*)(wr1 + j + 2);
            u64 w2a = *(const u64*)(wr2 + j), w2b = *(const u64*)(wr2 + j + 2);
            u64 w3a = *(const u64*)(wr3 + j), w3b = *(const u64*)(wr3 + j + 2);
            vacc[0][0] = ffma2(w0a, va0, vacc[0][0]);
            vacc[0][0] = ffma2(w0b, va1, vacc[0][0]);
            vacc[0][1] = ffma2(w0a, vb0, vacc[0][1]);
            vacc[0][1] = ffma2(w0b, vb1, vacc[0][1]);
            vacc[1][0] = ffma2(w1a, va0, vacc[1][0]);
            vacc[1][0] = ffma2(w1b, va1, vacc[1][0]);
            vacc[1][1] = ffma2(w1a, vb0, vacc[1][1]);
            vacc[1][1] = ffma2(w1b, vb1, vacc[1][1]);
            vacc[2][0] = ffma2(w2a, va0, vacc[2][0]);
            vacc[2][0] = ffma2(w2b, va1, vacc[2][0]);
            vacc[2][1] = ffma2(w2a, vb0, vacc[2][1]);
            vacc[2][1] = ffma2(w2b, vb1, vacc[2][1]);
            vacc[3][0] = ffma2(w3a, va0, vacc[3][0]);
            vacc[3][0] = ffma2(w3b, va1, vacc[3][0]);
            vacc[3][1] = ffma2(w3a, vb0, vacc[3][1]);
            vacc[3][1] = ffma2(w3b, vb1, vacc[3][1]);
        }
        __syncthreads();
    }

    // ============ PHASE 4: rel_v epilogue (acc paired over r) ============
    // stage relvT[d][r] into KV (stride VST)
    for (int e = tid; e < R * 64; e += 256) {
        int r = e >> 6, d = e & 63;
        KV[d * VST + r] = relv[e];
    }
    __syncthreads();

    {
        const float* u0 = biasW + (ty * 4 + 0) * 132;
        const float* u1 = biasW + (ty * 4 + 1) * 132;
        const float* u2 = biasW + (ty * 4 + 2) * 132;
        const float* u3 = biasW + (ty * 4 + 3) * 132;
        const float* vp0 = KV + d0 * VST;
        const float* vp1 = KV + d1 * VST;
#pragma unroll 4
        for (int rq = 0; rq < 128; rq += 4) {
            u64 va0 = *(const u64*)(vp0 + rq);
            u64 va1 = *(const u64*)(vp0 + rq + 2);
            u64 vb0 = *(const u64*)(vp1 + rq);
            u64 vb1 = *(const u64*)(vp1 + rq + 2);
            u64 w0a = *(const u64*)(u0 + rq), w0b = *(const u64*)(u0 + rq + 2);
            u64 w1a = *(const u64*)(u1 + rq), w1b = *(const u64*)(u1 + rq + 2);
            u64 w2a = *(const u64*)(u2 + rq), w2b = *(const u64*)(u2 + rq + 2);
            u64 w3a = *(const u64*)(u3 + rq), w3b = *(const u64*)(u3 + rq + 2);
            vacc[0][0] = ffma2(w0a, va0, vacc[0][0]);
            vacc[0][0] = ffma2(w0b, va1, vacc[0][0]);
            vacc[0][1] = ffma2(w0a, vb0, vacc[0][1]);
            vacc[0][1] = ffma2(w0b, vb1, vacc[0][1]);
            vacc[1][0] = ffma2(w1a, va0, vacc[1][0]);
            vacc[1][0] = ffma2(w1b, va1, vacc[1][0]);
            vacc[1][1] = ffma2(w1a, vb0, vacc[1][1]);
            vacc[1][1] = ffma2(w1b, vb1, vacc[1][1]);
            vacc[2][0] = ffma2(w2a, va0, vacc[2][0]);
            vacc[2][0] = ffma2(w2b, va1, vacc[2][0]);
            vacc[2][1] = ffma2(w2a, vb0, vacc[2][1]);
            vacc[2][1] = ffma2(w2b, vb1, vacc[2][1]);
            vacc[3][0] = ffma2(w3a, va0, vacc[3][0]);
            vacc[3][0] = ffma2(w3b, va1, vacc[3][0]);
            vacc[3][1] = ffma2(w3a, vb0, vacc[3][1]);
            vacc[3][1] = ffma2(w3b, vb1, vacc[3][1]);
        }
    }

    // ---- writeout: unpack, add r=128 tail term, scale by 1/sum ----
#pragma unroll
    for (int i = 0; i < 4; ++i) {
        const int il = ty * 4 + i;
        const int gi = i0 + il;
        const float wt = biasW[il * 132 + 128];   // raw tail wsum
        const float iv = invS[il];
        float2 sa = up2(vacc[i][0]);
        float2 sb = up2(vacc[i][1]);
        float o0 = (sa.x + sa.y + wt * KV[d0 * VST + 128]) * iv;
        float o1 = (sb.x + sb.y + wt * KV[d1 * VST + 128]) * iv;
        float* ob = g_o + (size_t)(b * L + gi) * D + h * DH;
        ob[d0] = o0;
        ob[d1] = o1;
    }
}

// ---------------------------------------------------------------------------
// Launch
// ---------------------------------------------------------------------------
extern "C" void kernel_launch(void* const* d_in, const int* in_sizes, int n_in,
                              void* d_out, int out_size) {
    const float* x    = (const float*)d_in[0];
    const float* Wq   = (const float*)d_in[1];
    const float* Wk   = (const float*)d_in[2];
    const float* Wv   = (const float*)d_in[3];
    const float* Wo   = (const float*)d_in[4];
    const float* relk = (const float*)d_in[5];
    const float* relv = (const float*)d_in[6];
    float* out = (float*)d_out;

    float *pq, *pk, *pv, *po;
    cudaGetSymbolAddress((void**)&pq, g_q);
    cudaGetSymbolAddress((void**)&pk, g_k);
    cudaGetSymbolAddress((void**)&pv, g_v);
    cudaGetSymbolAddress((void**)&po, g_o);
    bf16 *xh, *xl, *wh, *wl;
    cudaGetSymbolAddress((void**)&xh, g_xh);
    cudaGetSymbolAddress((void**)&xl, g_xl);
    cudaGetSymbolAddress((void**)&wh, g_wh);
    cudaGetSymbolAddress((void**)&wl, g_wl);

    cudaFuncSetAttribute(mega_attn_kernel,
                         cudaFuncAttributeMaxDynamicSharedMemorySize,
                         (int)FUSED_SMEM);

    const dim3 gg(D / 128, NT / 128);       // (8, 16) = 128 CTAs
    const dim3 gt(32, 32);
    const dim3 bt(32, 8);
    const int splitBlocks = (NT * D) / (256 * 4);   // 2048
    const float qscale = 0.125f;            // DH^-0.5

    // x split once, reused for q/k/v
    split_kernel<<<splitBlocks, 256>>>(x, xh, xl);

    splitT_kernel<<<gt, bt>>>(Wq, wh, wl);
    hgemm3x<<<gg, 256>>>(xh, xl, wh, wl, pq, NT, D, D, qscale);

    splitT_kernel<<<gt, bt>>>(Wk, wh, wl);
    hgemm3x<<<gg, 256>>>(xh, xl, wh, wl, pk, NT, D, D, 1.0f);

    splitT_kernel<<<gt, bt>>>(Wv, wh, wl);
    hgemm3x<<<gg, 256>>>(xh, xl, wh, wl, pv, NT, D, D, 1.0f);

    relq_kernel<<<dim3(L / 32, BH), 256>>>(relk);

    // fully fused attention: logits + softmax + wsum + A@V + rel_v
    mega_attn_kernel<<<dim3(L / 32, BH), 256, FUSED_SMEM>>>(relv);

    // final projection
    split_kernel<<<splitBlocks, 256>>>(po, xh, xl);
    splitT_kernel<<<gt, bt>>>(Wo, wh, wl);
    hgemm3x<<<gg, 256>>>(xh, xl, wh, wl, out, NT, D, D, 1.0f);
}

// round 12
// speedup vs baseline: 1.1024x; 1.0342x over previous
#include <cuda_runtime.h>
#include <cuda_bf16.h>
#include <cstdint>

// ---------------------------------------------------------------------------
// MultiHead2DAttention (Shaw relative positions, T2T variant)
// B=2, L=1024, D=1024, H=16, DH=64, M=64, R=129
// Round 11: q/k/v projections merged into ONE 2048x3072x1024 GEMM (fills the
// 148-SM chip instead of 3x 128-CTA waves); weight transposes batched into a
// single z-grid launch; q-scale folded into attention-side q staging.
// Attention middle (mega kernel) unchanged from the passing R10 version.
// Launch order places mega_attn_kernel at ncu's -s 5 sample slot.
// ---------------------------------------------------------------------------

namespace {
constexpr int B  = 2;
constexpr int L  = 1024;
constexpr int D  = 1024;
constexpr int H  = 16;
constexpr int DH = 64;
constexpr int MREL = 64;
constexpr int R  = 2 * MREL + 1;   // 129
constexpr int RP = 132;            // padded row stride for relq
constexpr int NT = B * L;          // 2048
constexpr int BH = B * H;          // 32
constexpr int KST = 132;           // K-stage stride (phase 1, float4 access)
constexpr int VST = 130;           // V-stage stride (phase 3/4, u64 access)
constexpr int QKV = 3 * D;         // 3072: row stride of fused qkv buffer
}

typedef __nv_bfloat16 bf16;
typedef unsigned long long u64;
typedef unsigned int u32;

// Scratch buffers (device globals: no allocations allowed)
__device__ float g_qkv[(size_t)NT * QKV];   // fused q|k|v, row stride 3072
__device__ float g_o[NT * D];
__device__ float g_relq[(size_t)BH * L * RP];

// bf16 split buffers
__device__ bf16 g_xh[NT * D];
__device__ bf16 g_xl[NT * D];
__device__ bf16 g_wh3[(size_t)3 * D * D];   // Wq|Wk|Wv transposed [3N][K]
__device__ bf16 g_wl3[(size_t)3 * D * D];
__device__ bf16 g_woh[D * D];               // Wo transposed [N][K]
__device__ bf16 g_wol[D * D];

// ---------------------------------------------------------------------------
// packed fp32 helpers
// ---------------------------------------------------------------------------
__device__ __forceinline__ u64 pk2(float x, float y) {
    u64 r;
    asm("mov.b64 %0, {%1, %2};" : "=l"(r) : "f"(x), "f"(y));
    return r;
}
__device__ __forceinline__ u64 dup2(float x) { return pk2(x, x); }
__device__ __forceinline__ u64 ffma2(u64 a, u64 b, u64 c) {
    u64 d;
    asm("fma.rn.f32x2 %0, %1, %2, %3;" : "=l"(d) : "l"(a), "l"(b), "l"(c));
    return d;
}
__device__ __forceinline__ float2 up2(u64 v) {
    float2 f;
    asm("mov.b64 {%0, %1}, %2;" : "=f"(f.x), "=f"(f.y) : "l"(v));
    return f;
}

// ---------------------------------------------------------------------------
// mma helper: D(f32) += A(bf16 16x16) * B(bf16 16x8)
// ---------------------------------------------------------------------------
__device__ __forceinline__ void mma16816(float* c, const u32* a, const u32* b) {
    asm volatile(
        "mma.sync.aligned.m16n8k16.row.col.f32.bf16.bf16.f32 "
        "{%0,%1,%2,%3},{%4,%5,%6,%7},{%8,%9},{%0,%1,%2,%3};"
        : "+f"(c[0]), "+f"(c[1]), "+f"(c[2]), "+f"(c[3])
        : "r"(a[0]), "r"(a[1]), "r"(a[2]), "r"(a[3]), "r"(b[0]), "r"(b[1]));
}

__device__ __forceinline__ void cp16(u32 smem_addr, const void* gptr) {
    asm volatile("cp.async.cg.shared.global [%0], [%1], 16;"
                 :: "r"(smem_addr), "l"(gptr));
}

// ---------------------------------------------------------------------------
// split: src fp32 -> hi/lo bf16 (elementwise)
// ---------------------------------------------------------------------------
__global__ __launch_bounds__(256) void split_kernel(const float* __restrict__ src,
                                                    bf16* __restrict__ hi,
                                                    bf16* __restrict__ lo) {
    int i = (blockIdx.x * 256 + threadIdx.x) * 4;
    float4 v = *(const float4*)(src + i);
    bf16 h0 = __float2bfloat16(v.x);
    bf16 h1 = __float2bfloat16(v.y);
    bf16 h2 = __float2bfloat16(v.z);
    bf16 h3 = __float2bfloat16(v.w);
    bf16 l0 = __float2bfloat16(v.x - __bfloat162float(h0));
    bf16 l1 = __float2bfloat16(v.y - __bfloat162float(h1));
    bf16 l2 = __float2bfloat16(v.z - __bfloat162float(h2));
    bf16 l3 = __float2bfloat16(v.w - __bfloat162float(h3));
    __nv_bfloat162* hp = (__nv_bfloat162*)(hi + i);
    __nv_bfloat162* lp = (__nv_bfloat162*)(lo + i);
    hp[0] = __nv_bfloat162(h0, h1);
    hp[1] = __nv_bfloat162(h2, h3);
    lp[0] = __nv_bfloat162(l0, l1);
    lp[1] = __nv_bfloat162(l2, l3);
}

// ---------------------------------------------------------------------------
// splitT3: three W[K][N] fp32 -> transposed hi/lo bf16 stacked [3N][K]
// grid (32, 32, 3), block (32, 8)
// ---------------------------------------------------------------------------
__global__ void splitT3_kernel(const float* __restrict__ W0,
                               const float* __restrict__ W1,
                               const float* __restrict__ W2,
                               bf16* __restrict__ th, bf16* __restrict__ tl) {
    __shared__ float ts[32][33];
    const int tx = threadIdx.x, ty = threadIdx.y;
    const int n0 = blockIdx.x * 32, k0 = blockIdx.y * 32;
    const int z = blockIdx.z;
    const float* W = (z == 0) ? W0 : (z == 1) ? W1 : W2;
    for (int r = ty; r < 32; r += 8)
        ts[r][tx] = W[(size_t)(k0 + r) * D + n0 + tx];
    __syncthreads();
    const size_t zofs = (size_t)z * D * D;
    for (int r = ty; r < 32; r += 8) {
        float v = ts[tx][r];
        bf16 h = __float2bfloat16(v);
        bf16 l = __float2bfloat16(v - __bfloat162float(h));
        th[zofs + (size_t)(n0 + r) * D + k0 + tx] = h;
        tl[zofs + (size_t)(n0 + r) * D + k0 + tx] = l;
    }
}

// single-weight variant (Wo)
__global__ void splitT_kernel(const float* __restrict__ W,
                              bf16* __restrict__ th, bf16* __restrict__ tl) {
    __shared__ float ts[32][33];
    const int tx = threadIdx.x, ty = threadIdx.y;
    const int n0 = blockIdx.x * 32, k0 = blockIdx.y * 32;
    for (int r = ty; r < 32; r += 8)
        ts[r][tx] = W[(size_t)(k0 + r) * D + n0 + tx];
    __syncthreads();
    for (int r = ty; r < 32; r += 8) {
        float v = ts[tx][r];
        bf16 h = __float2bfloat16(v);
        bf16 l = __float2bfloat16(v - __bfloat162float(h));
        th[(size_t)(n0 + r) * D + k0 + tx] = h;
        tl[(size_t)(n0 + r) * D + k0 + tx] = l;
    }
}

// ---------------------------------------------------------------------------
// hgemm3x: C[M,N] = A[M,K] @ B[K,N]  (A hi/lo bf16 row-major, B hi/lo bf16
// transposed [N][K]). 3-pass compensated bf16 MMA. Works for any Nd mult 128.
// ---------------------------------------------------------------------------
__global__ __launch_bounds__(256) void hgemm3x(const bf16* __restrict__ Ah,
                                               const bf16* __restrict__ Al,
                                               const bf16* __restrict__ Bh,
                                               const bf16* __restrict__ Bl,
                                               float* __restrict__ C,
                                               int Md, int Nd, int Kd) {
    constexpr int STR = 24;
    constexpr int STG = 128 * STR;
    __shared__ bf16 As_h[2 * STG];
    __shared__ bf16 As_l[2 * STG];
    __shared__ bf16 Bs_h[2 * STG];
    __shared__ bf16 Bs_l[2 * STG];

    const int tid = threadIdx.x;
    const int bm = blockIdx.y * 128;
    const int bn = blockIdx.x * 128;
    const int wid = tid >> 5;
    const int lane = tid & 31;
    const int g = lane >> 2;
    const int tg = lane & 3;
    const int wm = (wid & 1) * 64;
    const int wn = (wid >> 1) * 32;

    const int lrow = tid >> 1;
    const int lseg = (tid & 1) * 8;
    const size_t aoff = (size_t)(bm + lrow) * Kd + lseg;
    const size_t boff = (size_t)(bn + lrow) * Kd + lseg;
    const u32 sdst = (u32)(lrow * STR + lseg) * 2;
    const u32 s_ah = (u32)__cvta_generic_to_shared(As_h);
    const u32 s_al = (u32)__cvta_generic_to_shared(As_l);
    const u32 s_bh = (u32)__cvta_generic_to_shared(Bs_h);
    const u32 s_bl = (u32)__cvta_generic_to_shared(Bs_l);

    float acc[4][4][4];
#pragma unroll
    for (int ma = 0; ma < 4; ++ma)
#pragma unroll
        for (int na = 0; na < 4; ++na)
#pragma unroll
            for (int e = 0; e < 4; ++e) acc[ma][na][e] = 0.0f;

    const int nT = Kd / 16;

    {
        const u32 o = sdst;
        cp16(s_ah + o, Ah + aoff);
        cp16(s_al + o, Al + aoff);
        cp16(s_bh + o, Bh + boff);
        cp16(s_bl + o, Bl + boff);
        asm volatile("cp.async.commit_group;");
    }

    for (int kt = 0; kt < nT; ++kt) {
        const int stg = kt & 1;
        if (kt + 1 < nT) {
            const u32 o = (u32)((stg ^ 1) * STG * 2) + sdst;
            const size_t ko = (size_t)(kt + 1) * 16;
            cp16(s_ah + o, Ah + aoff + ko);
            cp16(s_al + o, Al + aoff + ko);
            cp16(s_bh + o, Bh + boff + ko);
            cp16(s_bl + o, Bl + boff + ko);
            asm volatile("cp.async.commit_group;");
            asm volatile("cp.async.wait_group 1;");
        } else {
            asm volatile("cp.async.wait_group 0;");
        }
        __syncthreads();

        const bf16* Abh = As_h + stg * STG;
        const bf16* Abl = As_l + stg * STG;
        const bf16* Bbh = Bs_h + stg * STG;
        const bf16* Bbl = Bs_l + stg * STG;

        u32 ah[4][4], al[4][4], bh[4][2], bl[4][2];
#pragma unroll
        for (int ma = 0; ma < 4; ++ma) {
            const int r0 = (wm + ma * 16 + g) * STR + 2 * tg;
            const int r1 = r0 + 8 * STR;
            ah[ma][0] = *(const u32*)(Abh + r0);
            ah[ma][1] = *(const u32*)(Abh + r1);
            ah[ma][2] = *(const u32*)(Abh + r0 + 8);
            ah[ma][3] = *(const u32*)(Abh + r1 + 8);
            al[ma][0] = *(const u32*)(Abl + r0);
            al[ma][1] = *(const u32*)(Abl + r1);
            al[ma][2] = *(const u32*)(Abl + r0 + 8);
            al[ma][3] = *(const u32*)(Abl + r1 + 8);
        }
#pragma unroll
        for (int na = 0; na < 4; ++na) {
            const int c0 = (wn + na * 8 + g) * STR + 2 * tg;
            bh[na][0] = *(const u32*)(Bbh + c0);
            bh[na][1] = *(const u32*)(Bbh + c0 + 8);
            bl[na][0] = *(const u32*)(Bbl + c0);
            bl[na][1] = *(const u32*)(Bbl + c0 + 8);
        }

#pragma unroll
        for (int ma = 0; ma < 4; ++ma)
#pragma unroll
            for (int na = 0; na < 4; ++na)
                mma16816(acc[ma][na], ah[ma], bh[na]);
#pragma unroll
        for (int ma = 0; ma < 4; ++ma)
#pragma unroll
            for (int na = 0; na < 4; ++na)
                mma16816(acc[ma][na], ah[ma], bl[na]);
#pragma unroll
        for (int ma = 0; ma < 4; ++ma)
#pragma unroll
            for (int na = 0; na < 4; ++na)
                mma16816(acc[ma][na], al[ma], bh[na]);
        __syncthreads();
    }

#pragma unroll
    for (int ma = 0; ma < 4; ++ma) {
#pragma unroll
        for (int na = 0; na < 4; ++na) {
            const int r0 = bm + wm + ma * 16 + g;
            const int c = bn + wn + na * 8 + 2 * tg;
            *(float2*)(C + (size_t)r0 * Nd + c) =
                make_float2(acc[ma][na][0], acc[ma][na][1]);
            *(float2*)(C + (size_t)(r0 + 8) * Nd + c) =
                make_float2(acc[ma][na][2], acc[ma][na][3]);
        }
    }
}

// ---------------------------------------------------------------------------
// relq[bh,i,r] = (q_scaled)[bh,i,:] . rel_k_table[r,:]
// q read from fused qkv buffer (stride 3072); 0.125 scale applied at stage.
// ---------------------------------------------------------------------------
__global__ __launch_bounds__(256) void relq_kernel(const float* __restrict__ relk) {
    __shared__ __align__(16) float qsT[64][36];
    __shared__ __align__(16) float tsT[64][132];

    const int tid = threadIdx.x;
    const int bh = blockIdx.y;
    const int b = bh >> 4;
    const int h = bh & 15;
    const int i0 = blockIdx.x * 32;
    const int tx = tid & 31;
    const int ty = tid >> 5;
    const float QS = 0.125f;

    {
        const int rI = tid >> 3;
        const int seg = (tid & 7) * 8;
        const float* qb = g_qkv + (size_t)(b * L + i0 + rI) * QKV + h * DH + seg;
        float4 v0 = *(const float4*)qb;
        float4 v1 = *(const float4*)(qb + 4);
        qsT[seg + 0][rI] = v0.x * QS; qsT[seg + 1][rI] = v0.y * QS;
        qsT[seg + 2][rI] = v0.z * QS; qsT[seg + 3][rI] = v0.w * QS;
        qsT[seg + 4][rI] = v1.x * QS; qsT[seg + 5][rI] = v1.y * QS;
        qsT[seg + 6][rI] = v1.z * QS; qsT[seg + 7][rI] = v1.w * QS;
    }
    for (int e = tid; e < R * 64; e += 256) {
        int r = e >> 6, d = e & 63;
        tsT[d][r] = relk[e];
    }
    __syncthreads();

    u64 acc2[2][4];
#pragma unroll
    for (int p = 0; p < 2; ++p)
#pragma unroll
        for (int j = 0; j < 4; ++j) acc2[p][j] = 0ull;

#pragma unroll 8
    for (int d = 0; d < 64; ++d) {
        const u64* ap = (const u64*)&qsT[d][ty * 4];
        u64 pa0 = ap[0], pa1 = ap[1];
        float4 bv = *(const float4*)&tsT[d][tx * 4];
        u64 pb0 = dup2(bv.x), pb1 = dup2(bv.y), pb2 = dup2(bv.z), pb3 = dup2(bv.w);
        acc2[0][0] = ffma2(pa0, pb0, acc2[0][0]);
        acc2[0][1] = ffma2(pa0, pb1, acc2[0][1]);
        acc2[0][2] = ffma2(pa0, pb2, acc2[0][2]);
        acc2[0][3] = ffma2(pa0, pb3, acc2[0][3]);
        acc2[1][0] = ffma2(pa1, pb0, acc2[1][0]);
        acc2[1][1] = ffma2(pa1, pb1, acc2[1][1]);
        acc2[1][2] = ffma2(pa1, pb2, acc2[1][2]);
        acc2[1][3] = ffma2(pa1, pb3, acc2[1][3]);
    }

#pragma unroll
    for (int p = 0; p < 2; ++p) {
        float2 c0 = up2(acc2[p][0]);
        float2 c1 = up2(acc2[p][1]);
        float2 c2 = up2(acc2[p][2]);
        float2 c3 = up2(acc2[p][3]);
        int gi = i0 + ty * 4 + 2 * p;
        float* o0 = g_relq + ((size_t)bh * L + gi) * RP + tx * 4;
        float* o1 = o0 + RP;
        *(float4*)o0 = make_float4(c0.x, c1.x, c2.x, c3.x);
        *(float4*)o1 = make_float4(c0.y, c1.y, c2.y, c3.y);
    }

    if (tid < 32) {
        float s = 0.0f;
#pragma unroll 8
        for (int d = 0; d < 64; ++d) s += qsT[d][tid] * tsT[d][128];
        g_relq[((size_t)bh * L + i0 + tid) * RP + 128] = s;
    }
}

// ---------------------------------------------------------------------------
// MEGA-fused attention (identical math to passing R10; q/k/v read from the
// fused buffer; q scaled 0.125 at stage).
// ---------------------------------------------------------------------------
namespace {
constexpr int SBS = 1032;  // Sb row stride (floats)
constexpr u32 FUSED_SMEM_FLOATS = 32 * SBS       // Sb
                                  + 64 * KST     // KV
                                  + 64 * 36      // QsT
                                  + 32 * 132     // biasW
                                  + 32;          // invS
constexpr u32 FUSED_SMEM = FUSED_SMEM_FLOATS * 4;
}

__global__ __launch_bounds__(256, 1) void mega_attn_kernel(
        const float* __restrict__ relv) {
    extern __shared__ float fs[];
    float* Sb    = fs;                       // [32][SBS]
    float* KV    = Sb + 32 * SBS;            // [64][KST] (K) / [64][VST] (V)
    float* QsT   = KV + 64 * KST;            // [64][36]
    float* biasW = QsT + 64 * 36;            // [32][132]
    float* invS  = biasW + 32 * 132;         // [32]

    const int tid = threadIdx.x;
    const int bh = blockIdx.y;
    const int b = bh >> 4;
    const int h = bh & 15;
    const int i0 = blockIdx.x * 32;
    const float QS = 0.125f;

    // ---- stage QsT (scaled) ----
    {
        const int rI = tid >> 3;
        const int seg = (tid & 7) * 8;
        const float* qb = g_qkv + (size_t)(b * L + i0 + rI) * QKV + h * DH + seg;
        float4 v0 = *(const float4*)qb;
        float4 v1 = *(const float4*)(qb + 4);
        QsT[(seg + 0) * 36 + rI] = v0.x * QS; QsT[(seg + 1) * 36 + rI] = v0.y * QS;
        QsT[(seg + 2) * 36 + rI] = v0.z * QS; QsT[(seg + 3) * 36 + rI] = v0.w * QS;
        QsT[(seg + 4) * 36 + rI] = v1.x * QS; QsT[(seg + 5) * 36 + rI] = v1.y * QS;
        QsT[(seg + 6) * 36 + rI] = v1.z * QS; QsT[(seg + 7) * 36 + rI] = v1.w * QS;
    }
    // ---- stage bias rows ----
    for (int e = tid; e < 32 * 132; e += 256) {
        int il = e / 132, r = e - il * 132;
        biasW[e] = (r < R) ? g_relq[((size_t)bh * L + i0 + il) * RP + r] : 0.0f;
    }

    const int ty = tid >> 5;
    const int tx = tid & 31;
    const int rJ = tid >> 1;
    const int segk = (tid & 1) * 32;
    const float* kbase = g_qkv + (size_t)(b * L + rJ) * QKV + D + h * DH + segk;
    const float* vbase = g_qkv + (size_t)(b * L + rJ) * QKV + 2 * D + h * DH + segk;

    float4 kreg[8];
#pragma unroll
    for (int u = 0; u < 8; ++u) kreg[u] = *(const float4*)(kbase + 4 * u);
    __syncthreads();

    // ============ PHASE 1: logits ============
    for (int jc = 0; jc < 8; ++jc) {
#pragma unroll
        for (int u = 0; u < 8; ++u) {
            int c = segk + 4 * u;
            KV[(c + 0) * KST + rJ] = kreg[u].x;
            KV[(c + 1) * KST + rJ] = kreg[u].y;
            KV[(c + 2) * KST + rJ] = kreg[u].z;
            KV[(c + 3) * KST + rJ] = kreg[u].w;
        }
        __syncthreads();
        if (jc < 7) {
            const float* kb = kbase + (size_t)(jc + 1) * 128 * QKV;
#pragma unroll
            for (int u = 0; u < 8; ++u) kreg[u] = *(const float4*)(kb + 4 * u);
        }

        u64 acc2[2][4];
#pragma unroll
        for (int p = 0; p < 2; ++p)
#pragma unroll
            for (int j = 0; j < 4; ++j) acc2[p][j] = 0ull;

#pragma unroll 8
        for (int d = 0; d < 64; ++d) {
            const u64* ap = (const u64*)&QsT[d * 36 + ty * 4];
            u64 pa0 = ap[0], pa1 = ap[1];
            float4 bv = *(const float4*)&KV[d * KST + tx * 4];
            u64 pb0 = dup2(bv.x), pb1 = dup2(bv.y);
            u64 pb2 = dup2(bv.z), pb3 = dup2(bv.w);
            acc2[0][0] = ffma2(pa0, pb0, acc2[0][0]);
            acc2[0][1] = ffma2(pa0, pb1, acc2[0][1]);
            acc2[0][2] = ffma2(pa0, pb2, acc2[0][2]);
            acc2[0][3] = ffma2(pa0, pb3, acc2[0][3]);
            acc2[1][0] = ffma2(pa1, pb0, acc2[1][0]);
            acc2[1][1] = ffma2(pa1, pb1, acc2[1][1]);
            acc2[1][2] = ffma2(pa1, pb2, acc2[1][2]);
            acc2[1][3] = ffma2(pa1, pb3, acc2[1][3]);
        }

        const int jb = jc * 128 + tx * 4;
#pragma unroll
        for (int p = 0; p < 2; ++p) {
            float2 c0 = up2(acc2[p][0]);
            float2 c1 = up2(acc2[p][1]);
            float2 c2 = up2(acc2[p][2]);
            float2 c3 = up2(acc2[p][3]);
#pragma unroll
            for (int e = 0; e < 2; ++e) {
                const int il = ty * 4 + 2 * p + e;
                const int gi = i0 + il;
                const float* brow = biasW + il * 132;
                int r0 = min(max(jb + 0 - gi, -MREL), MREL) + MREL;
                int r1 = min(max(jb + 1 - gi, -MREL), MREL) + MREL;
                int r2 = min(max(jb + 2 - gi, -MREL), MREL) + MREL;
                int r3 = min(max(jb + 3 - gi, -MREL), MREL) + MREL;
                float4 o;
                o.x = (e ? c0.y : c0.x) + brow[r0];
                o.y = (e ? c1.y : c1.x) + brow[r1];
                o.z = (e ? c2.y : c2.x) + brow[r2];
                o.w = (e ? c3.y : c3.x) + brow[r3];
                *(float4*)&Sb[il * SBS + jb] = o;
            }
        }
        __syncthreads();
    }

    // ============ PHASE 2: softmax + raw wsum ============
    {
        const int row = tid >> 3;
        const int ts = tid & 7;
        const int gi = i0 + row;
        float* srow = Sb + row * SBS;

        float m = -3.0e38f;
#pragma unroll 8
        for (int c = 0; c < 32; ++c) {
            float4 v = *(const float4*)&srow[ts * 4 + c * 32];
            m = fmaxf(m, fmaxf(fmaxf(v.x, v.y), fmaxf(v.z, v.w)));
        }
#pragma unroll
        for (int o = 4; o > 0; o >>= 1)
            m = fmaxf(m, __shfl_xor_sync(0xffffffffu, m, o));

        float s = 0.0f;
#pragma unroll 8
        for (int c = 0; c < 32; ++c) {
            float4 v = *(float4*)&srow[ts * 4 + c * 32];
            v.x = __expf(v.x - m); v.y = __expf(v.y - m);
            v.z = __expf(v.z - m); v.w = __expf(v.w - m);
            *(float4*)&srow[ts * 4 + c * 32] = v;
            s += v.x + v.y + v.z + v.w;
        }
#pragma unroll
        for (int o = 4; o > 0; o >>= 1) s += __shfl_xor_sync(0xffffffffu, s, o);
        if (ts == 0) invS[row] = 1.0f / s;

        float hp = 0.0f, tp = 0.0f;
        for (int j = ts; j <= gi - MREL; j += 8) hp += srow[j];
        for (int j = gi + MREL + ts; j < L; j += 8) tp += srow[j];
#pragma unroll
        for (int o = 4; o > 0; o >>= 1) {
            hp += __shfl_xor_sync(0xffffffffu, hp, o);
            tp += __shfl_xor_sync(0xffffffffu, tp, o);
        }
        __syncthreads();

        float* wrow = biasW + row * 132;
#pragma unroll
        for (int k = 0; k < 16; ++k) {
            int r = 1 + ts * 16 + k;
            if (r < 128) {
                int j = gi + r - 64;
                wrow[r] = (j >= 0 && j < L) ? srow[j] : 0.0f;
            }
        }
        if (ts == 0) {
            wrow[0] = hp;
            wrow[128] = tp;
        }
    }

    // ============ PHASE 3: O = exp @ V ============
    u64 vacc[4][2];
#pragma unroll
    for (int i = 0; i < 4; ++i) { vacc[i][0] = 0ull; vacc[i][1] = 0ull; }

    const float* wr0 = Sb + (ty * 4 + 0) * SBS;
    const float* wr1 = Sb + (ty * 4 + 1) * SBS;
    const float* wr2 = Sb + (ty * 4 + 2) * SBS;
    const float* wr3 = Sb + (ty * 4 + 3) * SBS;
    const int d0 = tx, d1 = tx + 32;

    float4 vreg[8];
#pragma unroll
    for (int u = 0; u < 8; ++u) vreg[u] = *(const float4*)(vbase + 4 * u);
    __syncthreads();

    for (int jc = 0; jc < 8; ++jc) {
#pragma unroll
        for (int u = 0; u < 8; ++u) {
            int c = segk + 4 * u;
            KV[(c + 0) * VST + rJ] = vreg[u].x;
            KV[(c + 1) * VST + rJ] = vreg[u].y;
            KV[(c + 2) * VST + rJ] = vreg[u].z;
            KV[(c + 3) * VST + rJ] = vreg[u].w;
        }
        __syncthreads();
        if (jc < 7) {
            const float* vb = vbase + (size_t)(jc + 1) * 128 * QKV;
#pragma unroll
            for (int u = 0; u < 8; ++u) vreg[u] = *(const float4*)(vb + 4 * u);
        }

        const int jbase = jc * 128;
        const float* vp0 = KV + d0 * VST;
        const float* vp1 = KV + d1 * VST;
#pragma unroll 4
        for (int jq = 0; jq < 128; jq += 4) {
            const int j = jbase + jq;
            u64 va0 = *(const u64*)(vp0 + jq);
            u64 va1 = *(const u64*)(vp0 + jq + 2);
            u64 vb0 = *(const u64*)(vp1 + jq);
            u64 vb1 = *(const u64*)(vp1 + jq + 2);
            u64 w0a = *(const u64*)(wr0 + j), w0b = *(const u64*)(wr0 + j + 2);
            u64 w1a = *(const u64*)(wr1 + j), w1b = *(const u64*)(wr1 + j + 2);
            u64 w2a = *(const u64*)(wr2 + j), w2b = *(const u64*)(wr2 + j + 2);
            u64 w3a = *(const u64*)(wr3 + j), w3b = *(const u64*)(wr3 + j + 2);
            vacc[0][0] = ffma2(w0a, va0, vacc[0][0]);
            vacc[0][0] = ffma2(w0b, va1, vacc[0][0]);
            vacc[0][1] = ffma2(w0a, vb0, vacc[0][1]);
            vacc[0][1] = ffma2(w0b, vb1, vacc[0][1]);
            vacc[1][0] = ffma2(w1a, va0, vacc[1][0]);
            vacc[1][0] = ffma2(w1b, va1, vacc[1][0]);
            vacc[1][1] = ffma2(w1a, vb0, vacc[1][1]);
            vacc[1][1] = ffma2(w1b, vb1, vacc[1][1]);
            vacc[2][0] = ffma2(w2a, va0, vacc[2][0]);
            vacc[2][0] = ffma2(w2b, va1, vacc[2][0]);
            vacc[2][1] = ffma2(w2a, vb0, vacc[2][1]);
            vacc[2][1] = ffma2(w2b, vb1, vacc[2][1]);
            vacc[3][0] = ffma2(w3a, va0, vacc[3][0]);
            vacc[3][0] = ffma2(w3b, va1, vacc[3][0]);
            vacc[3][1] = ffma2(w3a, vb0, vacc[3][1]);
            vacc[3][1] = ffma2(w3b, vb1, vacc[3][1]);
        }
        __syncthreads();
    }

    // ============ PHASE 4: rel_v epilogue ============
    for (int e = tid; e < R * 64; e += 256) {
        int r = e >> 6, d = e & 63;
        KV[d * VST + r] = relv[e];
    }
    __syncthreads();

    {
        const float* u0 = biasW + (ty * 4 + 0) * 132;
        const float* u1 = biasW + (ty * 4 + 1) * 132;
        const float* u2 = biasW + (ty * 4 + 2) * 132;
        const float* u3 = biasW + (ty * 4 + 3) * 132;
        const float* vp0 = KV + d0 * VST;
        const float* vp1 = KV + d1 * VST;
#pragma unroll 4
        for (int rq = 0; rq < 128; rq += 4) {
            u64 va0 = *(const u64*)(vp0 + rq);
            u64 va1 = *(const u64*)(vp0 + rq + 2);
            u64 vb0 = *(const u64*)(vp1 + rq);
            u64 vb1 = *(const u64*)(vp1 + rq + 2);
            u64 w0a = *(const u64*)(u0 + rq), w0b = *(const u64*)(u0 + rq + 2);
            u64 w1a = *(const u64*)(u1 + rq), w1b = *(const u64*)(u1 + rq + 2);
            u64 w2a = *(const u64*)(u2 + rq), w2b = *(const u64*)(u2 + rq + 2);
            u64 w3a = *(const u64*)(u3 + rq), w3b = *(const u64*)(u3 + rq + 2);
            vacc[0][0] = ffma2(w0a, va0, vacc[0][0]);
            vacc[0][0] = ffma2(w0b, va1, vacc[0][0]);
            vacc[0][1] = ffma2(w0a, vb0, vacc[0][1]);
            vacc[0][1] = ffma2(w0b, vb1, vacc[0][1]);
            vacc[1][0] = ffma2(w1a, va0, vacc[1][0]);
            vacc[1][0] = ffma2(w1b, va1, vacc[1][0]);
            vacc[1][1] = ffma2(w1a, vb0, vacc[1][1]);
            vacc[1][1] = ffma2(w1b, vb1, vacc[1][1]);
            vacc[2][0] = ffma2(w2a, va0, vacc[2][0]);
            vacc[2][0] = ffma2(w2b, va1, vacc[2][0]);
            vacc[2][1] = ffma2(w2a, vb0, vacc[2][1]);
            vacc[2][1] = ffma2(w2b, vb1, vacc[2][1]);
            vacc[3][0] = ffma2(w3a, va0, vacc[3][0]);
            vacc[3][0] = ffma2(w3b, va1, vacc[3][0]);
            vacc[3][1] = ffma2(w3a, vb0, vacc[3][1]);
            vacc[3][1] = ffma2(w3b, vb1, vacc[3][1]);
        }
    }

    // ---- writeout ----
#pragma unroll
    for (int i = 0; i < 4; ++i) {
        const int il = ty * 4 + i;
        const int gi = i0 + il;
        const float wt = biasW[il * 132 + 128];
        const float iv = invS[il];
        float2 sa = up2(vacc[i][0]);
        float2 sb = up2(vacc[i][1]);
        float o0 = (sa.x + sa.y + wt * KV[d0 * VST + 128]) * iv;
        float o1 = (sb.x + sb.y + wt * KV[d1 * VST + 128]) * iv;
        float* ob = g_o + (size_t)(b * L + gi) * D + h * DH;
        ob[d0] = o0;
        ob[d1] = o1;
    }
}

// ---------------------------------------------------------------------------
// Launch
// ---------------------------------------------------------------------------
extern "C" void kernel_launch(void* const* d_in, const int* in_sizes, int n_in,
                              void* d_out, int out_size) {
    const float* x    = (const float*)d_in[0];
    const float* Wq   = (const float*)d_in[1];
    const float* Wk   = (const float*)d_in[2];
    const float* Wv   = (const float*)d_in[3];
    const float* Wo   = (const float*)d_in[4];
    const float* relk = (const float*)d_in[5];
    const float* relv = (const float*)d_in[6];
    float* out = (float*)d_out;

    float *pqkv, *po;
    cudaGetSymbolAddress((void**)&pqkv, g_qkv);
    cudaGetSymbolAddress((void**)&po, g_o);
    bf16 *xh, *xl, *wh3, *wl3, *woh, *wol;
    cudaGetSymbolAddress((void**)&xh, g_xh);
    cudaGetSymbolAddress((void**)&xl, g_xl);
    cudaGetSymbolAddress((void**)&wh3, g_wh3);
    cudaGetSymbolAddress((void**)&wl3, g_wl3);
    cudaGetSymbolAddress((void**)&woh, g_woh);
    cudaGetSymbolAddress((void**)&wol, g_wol);

    cudaFuncSetAttribute(mega_attn_kernel,
                         cudaFuncAttributeMaxDynamicSharedMemorySize,
                         (int)FUSED_SMEM);

    const dim3 gqkv(QKV / 128, NT / 128);   // (24, 16) = 384 CTAs
    const dim3 gout(D / 128, NT / 128);     // (8, 16)  = 128 CTAs
    const dim3 gt(32, 32);
    const dim3 gt3(32, 32, 3);
    const dim3 bt(32, 8);
    const int splitBlocks = (NT * D) / (256 * 4);   // 2048

    // launch 0: x split (reused across qkv)
    split_kernel<<<splitBlocks, 256>>>(x, xh, xl);
    // launch 1: batched Wq/Wk/Wv transpose+split
    splitT3_kernel<<<gt3, bt>>>(Wq, Wk, Wv, wh3, wl3);
    // launch 2: Wo transpose+split (hoisted; independent)
    splitT_kernel<<<gt, bt>>>(Wo, woh, wol);
    // launch 3: ONE fused qkv GEMM (2048 x 3072 x 1024)
    hgemm3x<<<gqkv, 256>>>(xh, xl, wh3, wl3, pqkv, NT, QKV, D);
    // launch 4: relq bias table
    relq_kernel<<<dim3(L / 32, BH), 256>>>(relk);
    // launch 5 (ncu -s 5 samples this): fused attention
    mega_attn_kernel<<<dim3(L / 32, BH), 256, FUSED_SMEM>>>(relv);
    // launches 6-7: output projection
    split_kernel<<<splitBlocks, 256>>>(po, xh, xl);
    hgemm3x<<<gout, 256>>>(xh, xl, woh, wol, out, NT, D, D);
}

// round 13
// speedup vs baseline: 1.1136x; 1.0101x over previous
#include <cuda_runtime.h>
#include <cuda_bf16.h>
#include <cstdint>

// ---------------------------------------------------------------------------
// MultiHead2DAttention (Shaw relative positions, T2T variant)
// B=2, L=1024, D=1024, H=16, DH=64, M=64, R=129
// Round 12: hgemm3x pipeline restructured -> 3-stage cp.async ring (prefetch
// distance 2, dynamic smem) with ONE __syncthreads per K-iteration (was 2 +
// exposed wait). ncu showed the GEMM barrier/latency-bound (tensor 41%,
// issue 21%). Everything else identical to passing R11 (784us).
// ---------------------------------------------------------------------------

namespace {
constexpr int B  = 2;
constexpr int L  = 1024;
constexpr int D  = 1024;
constexpr int H  = 16;
constexpr int DH = 64;
constexpr int MREL = 64;
constexpr int R  = 2 * MREL + 1;   // 129
constexpr int RP = 132;            // padded row stride for relq
constexpr int NT = B * L;          // 2048
constexpr int BH = B * H;          // 32
constexpr int KST = 132;           // K-stage stride (phase 1, float4 access)
constexpr int VST = 130;           // V-stage stride (phase 3/4, u64 access)
constexpr int QKV = 3 * D;         // 3072: row stride of fused qkv buffer
}

typedef __nv_bfloat16 bf16;
typedef unsigned long long u64;
typedef unsigned int u32;

// Scratch buffers (device globals: no allocations allowed)
__device__ float g_qkv[(size_t)NT * QKV];   // fused q|k|v, row stride 3072
__device__ float g_o[NT * D];
__device__ float g_relq[(size_t)BH * L * RP];

// bf16 split buffers
__device__ bf16 g_xh[NT * D];
__device__ bf16 g_xl[NT * D];
__device__ bf16 g_wh3[(size_t)3 * D * D];   // Wq|Wk|Wv transposed [3N][K]
__device__ bf16 g_wl3[(size_t)3 * D * D];
__device__ bf16 g_woh[D * D];               // Wo transposed [N][K]
__device__ bf16 g_wol[D * D];

// ---------------------------------------------------------------------------
// packed fp32 helpers
// ---------------------------------------------------------------------------
__device__ __forceinline__ u64 pk2(float x, float y) {
    u64 r;
    asm("mov.b64 %0, {%1, %2};" : "=l"(r) : "f"(x), "f"(y));
    return r;
}
__device__ __forceinline__ u64 dup2(float x) { return pk2(x, x); }
__device__ __forceinline__ u64 ffma2(u64 a, u64 b, u64 c) {
    u64 d;
    asm("fma.rn.f32x2 %0, %1, %2, %3;" : "=l"(d) : "l"(a), "l"(b), "l"(c));
    return d;
}
__device__ __forceinline__ float2 up2(u64 v) {
    float2 f;
    asm("mov.b64 {%0, %1}, %2;" : "=f"(f.x), "=f"(f.y) : "l"(v));
    return f;
}

// ---------------------------------------------------------------------------
// mma helper: D(f32) += A(bf16 16x16) * B(bf16 16x8)
// ---------------------------------------------------------------------------
__device__ __forceinline__ void mma16816(float* c, const u32* a, const u32* b) {
    asm volatile(
        "mma.sync.aligned.m16n8k16.row.col.f32.bf16.bf16.f32 "
        "{%0,%1,%2,%3},{%4,%5,%6,%7},{%8,%9},{%0,%1,%2,%3};"
        : "+f"(c[0]), "+f"(c[1]), "+f"(c[2]), "+f"(c[3])
        : "r"(a[0]), "r"(a[1]), "r"(a[2]), "r"(a[3]), "r"(b[0]), "r"(b[1]));
}

__device__ __forceinline__ void cp16(u32 smem_addr, const void* gptr) {
    asm volatile("cp.async.cg.shared.global [%0], [%1], 16;"
                 :: "r"(smem_addr), "l"(gptr));
}

// ---------------------------------------------------------------------------
// split: src fp32 -> hi/lo bf16 (elementwise)
// ---------------------------------------------------------------------------
__global__ __launch_bounds__(256) void split_kernel(const float* __restrict__ src,
                                                    bf16* __restrict__ hi,
                                                    bf16* __restrict__ lo) {
    int i = (blockIdx.x * 256 + threadIdx.x) * 4;
    float4 v = *(const float4*)(src + i);
    bf16 h0 = __float2bfloat16(v.x);
    bf16 h1 = __float2bfloat16(v.y);
    bf16 h2 = __float2bfloat16(v.z);
    bf16 h3 = __float2bfloat16(v.w);
    bf16 l0 = __float2bfloat16(v.x - __bfloat162float(h0));
    bf16 l1 = __float2bfloat16(v.y - __bfloat162float(h1));
    bf16 l2 = __float2bfloat16(v.z - __bfloat162float(h2));
    bf16 l3 = __float2bfloat16(v.w - __bfloat162float(h3));
    __nv_bfloat162* hp = (__nv_bfloat162*)(hi + i);
    __nv_bfloat162* lp = (__nv_bfloat162*)(lo + i);
    hp[0] = __nv_bfloat162(h0, h1);
    hp[1] = __nv_bfloat162(h2, h3);
    lp[0] = __nv_bfloat162(l0, l1);
    lp[1] = __nv_bfloat162(l2, l3);
}

// ---------------------------------------------------------------------------
// splitT3: three W[K][N] fp32 -> transposed hi/lo bf16 stacked [3N][K]
// ---------------------------------------------------------------------------
__global__ void splitT3_kernel(const float* __restrict__ W0,
                               const float* __restrict__ W1,
                               const float* __restrict__ W2,
                               bf16* __restrict__ th, bf16* __restrict__ tl) {
    __shared__ float ts[32][33];
    const int tx = threadIdx.x, ty = threadIdx.y;
    const int n0 = blockIdx.x * 32, k0 = blockIdx.y * 32;
    const int z = blockIdx.z;
    const float* W = (z == 0) ? W0 : (z == 1) ? W1 : W2;
    for (int r = ty; r < 32; r += 8)
        ts[r][tx] = W[(size_t)(k0 + r) * D + n0 + tx];
    __syncthreads();
    const size_t zofs = (size_t)z * D * D;
    for (int r = ty; r < 32; r += 8) {
        float v = ts[tx][r];
        bf16 h = __float2bfloat16(v);
        bf16 l = __float2bfloat16(v - __bfloat162float(h));
        th[zofs + (size_t)(n0 + r) * D + k0 + tx] = h;
        tl[zofs + (size_t)(n0 + r) * D + k0 + tx] = l;
    }
}

// single-weight variant (Wo)
__global__ void splitT_kernel(const float* __restrict__ W,
                              bf16* __restrict__ th, bf16* __restrict__ tl) {
    __shared__ float ts[32][33];
    const int tx = threadIdx.x, ty = threadIdx.y;
    const int n0 = blockIdx.x * 32, k0 = blockIdx.y * 32;
    for (int r = ty; r < 32; r += 8)
        ts[r][tx] = W[(size_t)(k0 + r) * D + n0 + tx];
    __syncthreads();
    for (int r = ty; r < 32; r += 8) {
        float v = ts[tx][r];
        bf16 h = __float2bfloat16(v);
        bf16 l = __float2bfloat16(v - __bfloat162float(h));
        th[(size_t)(n0 + r) * D + k0 + tx] = h;
        tl[(size_t)(n0 + r) * D + k0 + tx] = l;
    }
}

// ---------------------------------------------------------------------------
// hgemm3x: C[M,N] = A[M,K] @ B[K,N]  (A hi/lo bf16 row-major, B hi/lo bf16
// transposed [N][K]). 3-pass compensated bf16 MMA.
// Round 12: 3-stage cp.async ring, prefetch distance 2, ONE sync per k-iter.
// Dynamic smem: 3 stages x 4 arrays x 128x24 bf16 = 73,728 B (2 CTAs/SM).
// ---------------------------------------------------------------------------
namespace {
constexpr int HG_STR = 24;                       // smem row stride (bf16)
constexpr u32 HG_TB = 128 * HG_STR * 2;          // bytes per array tile: 6144
constexpr u32 HG_STAGE_B = 4 * HG_TB;            // per-stage bytes: 24576
constexpr u32 HG_SMEM = 3 * HG_STAGE_B;          // 73728
}

__global__ __launch_bounds__(256) void hgemm3x(const bf16* __restrict__ Ah,
                                               const bf16* __restrict__ Al,
                                               const bf16* __restrict__ Bh,
                                               const bf16* __restrict__ Bl,
                                               float* __restrict__ C,
                                               int Md, int Nd, int Kd) {
    extern __shared__ __align__(16) bf16 hsm[];
    const u32 sbase = (u32)__cvta_generic_to_shared(hsm);

    const int tid = threadIdx.x;
    const int bm = blockIdx.y * 128;
    const int bn = blockIdx.x * 128;
    const int wid = tid >> 5;
    const int lane = tid & 31;
    const int g = lane >> 2;
    const int tg = lane & 3;
    const int wm = (wid & 1) * 64;
    const int wn = (wid >> 1) * 32;

    const int lrow = tid >> 1;
    const int lseg = (tid & 1) * 8;
    const size_t aoff = (size_t)(bm + lrow) * Kd + lseg;
    const size_t boff = (size_t)(bn + lrow) * Kd + lseg;
    const u32 sdst = (u32)(lrow * HG_STR + lseg) * 2;   // byte offset in array

    float acc[4][4][4];
#pragma unroll
    for (int ma = 0; ma < 4; ++ma)
#pragma unroll
        for (int na = 0; na < 4; ++na)
#pragma unroll
            for (int e = 0; e < 4; ++e) acc[ma][na][e] = 0.0f;

    const int nT = Kd / 16;

    auto stage_tile = [&](int kt, int slot) {
        const u32 o = sbase + (u32)slot * HG_STAGE_B + sdst;
        const size_t ko = (size_t)kt * 16;
        cp16(o + 0 * HG_TB, Ah + aoff + ko);
        cp16(o + 1 * HG_TB, Al + aoff + ko);
        cp16(o + 2 * HG_TB, Bh + boff + ko);
        cp16(o + 3 * HG_TB, Bl + boff + ko);
        asm volatile("cp.async.commit_group;");
    };

    // prologue: prefetch tiles 0 and 1
    stage_tile(0, 0);
    if (nT > 1) stage_tile(1, 1);

    int slot = 0;
    for (int kt = 0; kt < nT; ++kt) {
        if (kt + 1 < nT) {
            asm volatile("cp.async.wait_group 1;" ::: "memory");
        } else {
            asm volatile("cp.async.wait_group 0;" ::: "memory");
        }
        __syncthreads();   // stage `slot` (tile kt) readable by all warps;
                           // also: all warps done reading slot (kt-1)%3,
                           // which the cp.async below (tile kt+2) overwrites.
        if (kt + 2 < nT) stage_tile(kt + 2, (slot + 2) % 3);

        const bf16* Abh = hsm + (size_t)slot * (HG_STAGE_B / 2);
        const bf16* Abl = Abh + HG_TB / 2;
        const bf16* Bbh = Abh + 2 * (HG_TB / 2);
        const bf16* Bbl = Abh + 3 * (HG_TB / 2);

        u32 ah[4][4], al[4][4], bh[4][2], bl[4][2];
#pragma unroll
        for (int ma = 0; ma < 4; ++ma) {
            const int r0 = (wm + ma * 16 + g) * HG_STR + 2 * tg;
            const int r1 = r0 + 8 * HG_STR;
            ah[ma][0] = *(const u32*)(Abh + r0);
            ah[ma][1] = *(const u32*)(Abh + r1);
            ah[ma][2] = *(const u32*)(Abh + r0 + 8);
            ah[ma][3] = *(const u32*)(Abh + r1 + 8);
            al[ma][0] = *(const u32*)(Abl + r0);
            al[ma][1] = *(const u32*)(Abl + r1);
            al[ma][2] = *(const u32*)(Abl + r0 + 8);
            al[ma][3] = *(const u32*)(Abl + r1 + 8);
        }
#pragma unroll
        for (int na = 0; na < 4; ++na) {
            const int c0 = (wn + na * 8 + g) * HG_STR + 2 * tg;
            bh[na][0] = *(const u32*)(Bbh + c0);
            bh[na][1] = *(const u32*)(Bbh + c0 + 8);
            bl[na][0] = *(const u32*)(Bbl + c0);
            bl[na][1] = *(const u32*)(Bbl + c0 + 8);
        }

#pragma unroll
        for (int ma = 0; ma < 4; ++ma)
#pragma unroll
            for (int na = 0; na < 4; ++na)
                mma16816(acc[ma][na], ah[ma], bh[na]);
#pragma unroll
        for (int ma = 0; ma < 4; ++ma)
#pragma unroll
            for (int na = 0; na < 4; ++na)
                mma16816(acc[ma][na], ah[ma], bl[na]);
#pragma unroll
        for (int ma = 0; ma < 4; ++ma)
#pragma unroll
            for (int na = 0; na < 4; ++na)
                mma16816(acc[ma][na], al[ma], bh[na]);

        slot = (slot + 1) % 3;
    }

#pragma unroll
    for (int ma = 0; ma < 4; ++ma) {
#pragma unroll
        for (int na = 0; na < 4; ++na) {
            const int r0 = bm + wm + ma * 16 + g;
            const int c = bn + wn + na * 8 + 2 * tg;
            *(float2*)(C + (size_t)r0 * Nd + c) =
                make_float2(acc[ma][na][0], acc[ma][na][1]);
            *(float2*)(C + (size_t)(r0 + 8) * Nd + c) =
                make_float2(acc[ma][na][2], acc[ma][na][3]);
        }
    }
}

// ---------------------------------------------------------------------------
// relq[bh,i,r] = (q_scaled)[bh,i,:] . rel_k_table[r,:]
// ---------------------------------------------------------------------------
__global__ __launch_bounds__(256) void relq_kernel(const float* __restrict__ relk) {
    __shared__ __align__(16) float qsT[64][36];
    __shared__ __align__(16) float tsT[64][132];

    const int tid = threadIdx.x;
    const int bh = blockIdx.y;
    const int b = bh >> 4;
    const int h = bh & 15;
    const int i0 = blockIdx.x * 32;
    const int tx = tid & 31;
    const int ty = tid >> 5;
    const float QS = 0.125f;

    {
        const int rI = tid >> 3;
        const int seg = (tid & 7) * 8;
        const float* qb = g_qkv + (size_t)(b * L + i0 + rI) * QKV + h * DH + seg;
        float4 v0 = *(const float4*)qb;
        float4 v1 = *(const float4*)(qb + 4);
        qsT[seg + 0][rI] = v0.x * QS; qsT[seg + 1][rI] = v0.y * QS;
        qsT[seg + 2][rI] = v0.z * QS; qsT[seg + 3][rI] = v0.w * QS;
        qsT[seg + 4][rI] = v1.x * QS; qsT[seg + 5][rI] = v1.y * QS;
        qsT[seg + 6][rI] = v1.z * QS; qsT[seg + 7][rI] = v1.w * QS;
    }
    for (int e = tid; e < R * 64; e += 256) {
        int r = e >> 6, d = e & 63;
        tsT[d][r] = relk[e];
    }
    __syncthreads();

    u64 acc2[2][4];
#pragma unroll
    for (int p = 0; p < 2; ++p)
#pragma unroll
        for (int j = 0; j < 4; ++j) acc2[p][j] = 0ull;

#pragma unroll 8
    for (int d = 0; d < 64; ++d) {
        const u64* ap = (const u64*)&qsT[d][ty * 4];
        u64 pa0 = ap[0], pa1 = ap[1];
        float4 bv = *(const float4*)&tsT[d][tx * 4];
        u64 pb0 = dup2(bv.x), pb1 = dup2(bv.y), pb2 = dup2(bv.z), pb3 = dup2(bv.w);
        acc2[0][0] = ffma2(pa0, pb0, acc2[0][0]);
        acc2[0][1] = ffma2(pa0, pb1, acc2[0][1]);
        acc2[0][2] = ffma2(pa0, pb2, acc2[0][2]);
        acc2[0][3] = ffma2(pa0, pb3, acc2[0][3]);
        acc2[1][0] = ffma2(pa1, pb0, acc2[1][0]);
        acc2[1][1] = ffma2(pa1, pb1, acc2[1][1]);
        acc2[1][2] = ffma2(pa1, pb2, acc2[1][2]);
        acc2[1][3] = ffma2(pa1, pb3, acc2[1][3]);
    }

#pragma unroll
    for (int p = 0; p < 2; ++p) {
        float2 c0 = up2(acc2[p][0]);
        float2 c1 = up2(acc2[p][1]);
        float2 c2 = up2(acc2[p][2]);
        float2 c3 = up2(acc2[p][3]);
        int gi = i0 + ty * 4 + 2 * p;
        float* o0 = g_relq + ((size_t)bh * L + gi) * RP + tx * 4;
        float* o1 = o0 + RP;
        *(float4*)o0 = make_float4(c0.x, c1.x, c2.x, c3.x);
        *(float4*)o1 = make_float4(c0.y, c1.y, c2.y, c3.y);
    }

    if (tid < 32) {
        float s = 0.0f;
#pragma unroll 8
        for (int d = 0; d < 64; ++d) s += qsT[d][tid] * tsT[d][128];
        g_relq[((size_t)bh * L + i0 + tid) * RP + 128] = s;
    }
}

// ---------------------------------------------------------------------------
// MEGA-fused attention (unchanged from passing R11)
// ---------------------------------------------------------------------------
namespace {
constexpr int SBS = 1032;  // Sb row stride (floats)
constexpr u32 FUSED_SMEM_FLOATS = 32 * SBS       // Sb
                                  + 64 * KST     // KV
                                  + 64 * 36      // QsT
                                  + 32 * 132     // biasW
                                  + 32;          // invS
constexpr u32 FUSED_SMEM = FUSED_SMEM_FLOATS * 4;
}

__global__ __launch_bounds__(256, 1) void mega_attn_kernel(
        const float* __restrict__ relv) {
    extern __shared__ float fs[];
    float* Sb    = fs;                       // [32][SBS]
    float* KV    = Sb + 32 * SBS;            // [64][KST] (K) / [64][VST] (V)
    float* QsT   = KV + 64 * KST;            // [64][36]
    float* biasW = QsT + 64 * 36;            // [32][132]
    float* invS  = biasW + 32 * 132;         // [32]

    const int tid = threadIdx.x;
    const int bh = blockIdx.y;
    const int b = bh >> 4;
    const int h = bh & 15;
    const int i0 = blockIdx.x * 32;
    const float QS = 0.125f;

    // ---- stage QsT (scaled) ----
    {
        const int rI = tid >> 3;
        const int seg = (tid & 7) * 8;
        const float* qb = g_qkv + (size_t)(b * L + i0 + rI) * QKV + h * DH + seg;
        float4 v0 = *(const float4*)qb;
        float4 v1 = *(const float4*)(qb + 4);
        QsT[(seg + 0) * 36 + rI] = v0.x * QS; QsT[(seg + 1) * 36 + rI] = v0.y * QS;
        QsT[(seg + 2) * 36 + rI] = v0.z * QS; QsT[(seg + 3) * 36 + rI] = v0.w * QS;
        QsT[(seg + 4) * 36 + rI] = v1.x * QS; QsT[(seg + 5) * 36 + rI] = v1.y * QS;
        QsT[(seg + 6) * 36 + rI] = v1.z * QS; QsT[(seg + 7) * 36 + rI] = v1.w * QS;
    }
    // ---- stage bias rows ----
    for (int e = tid; e < 32 * 132; e += 256) {
        int il = e / 132, r = e - il * 132;
        biasW[e] = (r < R) ? g_relq[((size_t)bh * L + i0 + il) * RP + r] : 0.0f;
    }

    const int ty = tid >> 5;
    const int tx = tid & 31;
    const int rJ = tid >> 1;
    const int segk = (tid & 1) * 32;
    const float* kbase = g_qkv + (size_t)(b * L + rJ) * QKV + D + h * DH + segk;
    const float* vbase = g_qkv + (size_t)(b * L + rJ) * QKV + 2 * D + h * DH + segk;

    float4 kreg[8];
#pragma unroll
    for (int u = 0; u < 8; ++u) kreg[u] = *(const float4*)(kbase + 4 * u);
    __syncthreads();

    // ============ PHASE 1: logits ============
    for (int jc = 0; jc < 8; ++jc) {
#pragma unroll
        for (int u = 0; u < 8; ++u) {
            int c = segk + 4 * u;
            KV[(c + 0) * KST + rJ] = kreg[u].x;
            KV[(c + 1) * KST + rJ] = kreg[u].y;
            KV[(c + 2) * KST + rJ] = kreg[u].z;
            KV[(c + 3) * KST + rJ] = kreg[u].w;
        }
        __syncthreads();
        if (jc < 7) {
            const float* kb = kbase + (size_t)(jc + 1) * 128 * QKV;
#pragma unroll
            for (int u = 0; u < 8; ++u) kreg[u] = *(const float4*)(kb + 4 * u);
        }

        u64 acc2[2][4];
#pragma unroll
        for (int p = 0; p < 2; ++p)
#pragma unroll
            for (int j = 0; j < 4; ++j) acc2[p][j] = 0ull;

#pragma unroll 8
        for (int d = 0; d < 64; ++d) {
            const u64* ap = (const u64*)&QsT[d * 36 + ty * 4];
            u64 pa0 = ap[0], pa1 = ap[1];
            float4 bv = *(const float4*)&KV[d * KST + tx * 4];
            u64 pb0 = dup2(bv.x), pb1 = dup2(bv.y);
            u64 pb2 = dup2(bv.z), pb3 = dup2(bv.w);
            acc2[0][0] = ffma2(pa0, pb0, acc2[0][0]);
            acc2[0][1] = ffma2(pa0, pb1, acc2[0][1]);
            acc2[0][2] = ffma2(pa0, pb2, acc2[0][2]);
            acc2[0][3] = ffma2(pa0, pb3, acc2[0][3]);
            acc2[1][0] = ffma2(pa1, pb0, acc2[1][0]);
            acc2[1][1] = ffma2(pa1, pb1, acc2[1][1]);
            acc2[1][2] = ffma2(pa1, pb2, acc2[1][2]);
            acc2[1][3] = ffma2(pa1, pb3, acc2[1][3]);
        }

        const int jb = jc * 128 + tx * 4;
#pragma unroll
        for (int p = 0; p < 2; ++p) {
            float2 c0 = up2(acc2[p][0]);
            float2 c1 = up2(acc2[p][1]);
            float2 c2 = up2(acc2[p][2]);
            float2 c3 = up2(acc2[p][3]);
#pragma unroll
            for (int e = 0; e < 2; ++e) {
                const int il = ty * 4 + 2 * p + e;
                const int gi = i0 + il;
                const float* brow = biasW + il * 132;
                int r0 = min(max(jb + 0 - gi, -MREL), MREL) + MREL;
                int r1 = min(max(jb + 1 - gi, -MREL), MREL) + MREL;
                int r2 = min(max(jb + 2 - gi, -MREL), MREL) + MREL;
                int r3 = min(max(jb + 3 - gi, -MREL), MREL) + MREL;
                float4 o;
                o.x = (e ? c0.y : c0.x) + brow[r0];
                o.y = (e ? c1.y : c1.x) + brow[r1];
                o.z = (e ? c2.y : c2.x) + brow[r2];
                o.w = (e ? c3.y : c3.x) + brow[r3];
                *(float4*)&Sb[il * SBS + jb] = o;
            }
        }
        __syncthreads();
    }

    // ============ PHASE 2: softmax + raw wsum ============
    {
        const int row = tid >> 3;
        const int ts = tid & 7;
        const int gi = i0 + row;
        float* srow = Sb + row * SBS;

        float m = -3.0e38f;
#pragma unroll 8
        for (int c = 0; c < 32; ++c) {
            float4 v = *(const float4*)&srow[ts * 4 + c * 32];
            m = fmaxf(m, fmaxf(fmaxf(v.x, v.y), fmaxf(v.z, v.w)));
        }
#pragma unroll
        for (int o = 4; o > 0; o >>= 1)
            m = fmaxf(m, __shfl_xor_sync(0xffffffffu, m, o));

        float s = 0.0f;
#pragma unroll 8
        for (int c = 0; c < 32; ++c) {
            float4 v = *(float4*)&srow[ts * 4 + c * 32];
            v.x = __expf(v.x - m); v.y = __expf(v.y - m);
            v.z = __expf(v.z - m); v.w = __expf(v.w - m);
            *(float4*)&srow[ts * 4 + c * 32] = v;
            s += v.x + v.y + v.z + v.w;
        }
#pragma unroll
        for (int o = 4; o > 0; o >>= 1) s += __shfl_xor_sync(0xffffffffu, s, o);
        if (ts == 0) invS[row] = 1.0f / s;

        float hp = 0.0f, tp = 0.0f;
        for (int j = ts; j <= gi - MREL; j += 8) hp += srow[j];
        for (int j = gi + MREL + ts; j < L; j += 8) tp += srow[j];
#pragma unroll
        for (int o = 4; o > 0; o >>= 1) {
            hp += __shfl_xor_sync(0xffffffffu, hp, o);
            tp += __shfl_xor_sync(0xffffffffu, tp, o);
        }
        __syncthreads();

        float* wrow = biasW + row * 132;
#pragma unroll
        for (int k = 0; k < 16; ++k) {
            int r = 1 + ts * 16 + k;
            if (r < 128) {
                int j = gi + r - 64;
                wrow[r] = (j >= 0 && j < L) ? srow[j] : 0.0f;
            }
        }
        if (ts == 0) {
            wrow[0] = hp;
            wrow[128] = tp;
        }
    }

    // ============ PHASE 3: O = exp @ V ============
    u64 vacc[4][2];
#pragma unroll
    for (int i = 0; i < 4; ++i) { vacc[i][0] = 0ull; vacc[i][1] = 0ull; }

    const float* wr0 = Sb + (ty * 4 + 0) * SBS;
    const float* wr1 = Sb + (ty * 4 + 1) * SBS;
    const float* wr2 = Sb + (ty * 4 + 2) * SBS;
    const float* wr3 = Sb + (ty * 4 + 3) * SBS;
    const int d0 = tx, d1 = tx + 32;

    float4 vreg[8];
#pragma unroll
    for (int u = 0; u < 8; ++u) vreg[u] = *(const float4*)(vbase + 4 * u);
    __syncthreads();

    for (int jc = 0; jc < 8; ++jc) {
#pragma unroll
        for (int u = 0; u < 8; ++u) {
            int c = segk + 4 * u;
            KV[(c + 0) * VST + rJ] = vreg[u].x;
            KV[(c + 1) * VST + rJ] = vreg[u].y;
            KV[(c + 2) * VST + rJ] = vreg[u].z;
            KV[(c + 3) * VST + rJ] = vreg[u].w;
        }
        __syncthreads();
        if (jc < 7) {
            const float* vb = vbase + (size_t)(jc + 1) * 128 * QKV;
#pragma unroll
            for (int u = 0; u < 8; ++u) vreg[u] = *(const float4*)(vb + 4 * u);
        }

        const int jbase = jc * 128;
        const float* vp0 = KV + d0 * VST;
        const float* vp1 = KV + d1 * VST;
#pragma unroll 4
        for (int jq = 0; jq < 128; jq += 4) {
            const int j = jbase + jq;
            u64 va0 = *(const u64*)(vp0 + jq);
            u64 va1 = *(const u64*)(vp0 + jq + 2);
            u64 vb0 = *(const u64*)(vp1 + jq);
            u64 vb1 = *(const u64*)(vp1 + jq + 2);
            u64 w0a = *(const u64*)(wr0 + j), w0b = *(const u64*)(wr0 + j + 2);
            u64 w1a = *(const u64*)(wr1 + j), w1b = *(const u64*)(wr1 + j + 2);
            u64 w2a = *(const u64*)(wr2 + j), w2b = *(const u64*)(wr2 + j + 2);
            u64 w3a = *(const u64*)(wr3 + j), w3b = *(const u64*)(wr3 + j + 2);
            vacc[0][0] = ffma2(w0a, va0, vacc[0][0]);
            vacc[0][0] = ffma2(w0b, va1, vacc[0][0]);
            vacc[0][1] = ffma2(w0a, vb0, vacc[0][1]);
            vacc[0][1] = ffma2(w0b, vb1, vacc[0][1]);
            vacc[1][0] = ffma2(w1a, va0, vacc[1][0]);
            vacc[1][0] = ffma2(w1b, va1, vacc[1][0]);
            vacc[1][1] = ffma2(w1a, vb0, vacc[1][1]);
            vacc[1][1] = ffma2(w1b, vb1, vacc[1][1]);
            vacc[2][0] = ffma2(w2a, va0, vacc[2][0]);
            vacc[2][0] = ffma2(w2b, va1, vacc[2][0]);
            vacc[2][1] = ffma2(w2a, vb0, vacc[2][1]);
            vacc[2][1] = ffma2(w2b, vb1, vacc[2][1]);
            vacc[3][0] = ffma2(w3a, va0, vacc[3][0]);
            vacc[3][0] = ffma2(w3b, va1, vacc[3][0]);
            vacc[3][1] = ffma2(w3a, vb0, vacc[3][1]);
            vacc[3][1] = ffma2(w3b, vb1, vacc[3][1]);
        }
        __syncthreads();
    }

    // ============ PHASE 4: rel_v epilogue ============
    for (int e = tid; e < R * 64; e += 256) {
        int r = e >> 6, d = e & 63;
        KV[d * VST + r] = relv[e];
    }
    __syncthreads();

    {
        const float* u0 = biasW + (ty * 4 + 0) * 132;
        const float* u1 = biasW + (ty * 4 + 1) * 132;
        const float* u2 = biasW + (ty * 4 + 2) * 132;
        const float* u3 = biasW + (ty * 4 + 3) * 132;
        const float* vp0 = KV + d0 * VST;
        const float* vp1 = KV + d1 * VST;
#pragma unroll 4
        for (int rq = 0; rq < 128; rq += 4) {
            u64 va0 = *(const u64*)(vp0 + rq);
            u64 va1 = *(const u64*)(vp0 + rq + 2);
            u64 vb0 = *(const u64*)(vp1 + rq);
            u64 vb1 = *(const u64*)(vp1 + rq + 2);
            u64 w0a = *(const u64*)(u0 + rq), w0b = *(const u64*)(u0 + rq + 2);
            u64 w1a = *(const u64*)(u1 + rq), w1b = *(const u64*)(u1 + rq + 2);
            u64 w2a = *(const u64*)(u2 + rq), w2b = *(const u64*)(u2 + rq + 2);
            u64 w3a = *(const u64*)(u3 + rq), w3b = *(const u64*)(u3 + rq + 2);
            vacc[0][0] = ffma2(w0a, va0, vacc[0][0]);
            vacc[0][0] = ffma2(w0b, va1, vacc[0][0]);
            vacc[0][1] = ffma2(w0a, vb0, vacc[0][1]);
            vacc[0][1] = ffma2(w0b, vb1, vacc[0][1]);
            vacc[1][0] = ffma2(w1a, va0, vacc[1][0]);
            vacc[1][0] = ffma2(w1b, va1, vacc[1][0]);
            vacc[1][1] = ffma2(w1a, vb0, vacc[1][1]);
            vacc[1][1] = ffma2(w1b, vb1, vacc[1][1]);
            vacc[2][0] = ffma2(w2a, va0, vacc[2][0]);
            vacc[2][0] = ffma2(w2b, va1, vacc[2][0]);
            vacc[2][1] = ffma2(w2a, vb0, vacc[2][1]);
            vacc[2][1] = ffma2(w2b, vb1, vacc[2][1]);
            vacc[3][0] = ffma2(w3a, va0, vacc[3][0]);
            vacc[3][0] = ffma2(w3b, va1, vacc[3][0]);
            vacc[3][1] = ffma2(w3a, vb0, vacc[3][1]);
            vacc[3][1] = ffma2(w3b, vb1, vacc[3][1]);
        }
    }

    // ---- writeout ----
#pragma unroll
    for (int i = 0; i < 4; ++i) {
        const int il = ty * 4 + i;
        const int gi = i0 + il;
        const float wt = biasW[il * 132 + 128];
        const float iv = invS[il];
        float2 sa = up2(vacc[i][0]);
        float2 sb = up2(vacc[i][1]);
        float o0 = (sa.x + sa.y + wt * KV[d0 * VST + 128]) * iv;
        float o1 = (sb.x + sb.y + wt * KV[d1 * VST + 128]) * iv;
        float* ob = g_o + (size_t)(b * L + gi) * D + h * DH;
        ob[d0] = o0;
        ob[d1] = o1;
    }
}

// ---------------------------------------------------------------------------
// Launch
// ---------------------------------------------------------------------------
extern "C" void kernel_launch(void* const* d_in, const int* in_sizes, int n_in,
                              void* d_out, int out_size) {
    const float* x    = (const float*)d_in[0];
    const float* Wq   = (const float*)d_in[1];
    const float* Wk   = (const float*)d_in[2];
    const float* Wv   = (const float*)d_in[3];
    const float* Wo   = (const float*)d_in[4];
    const float* relk = (const float*)d_in[5];
    const float* relv = (const float*)d_in[6];
    float* out = (float*)d_out;

    float *pqkv, *po;
    cudaGetSymbolAddress((void**)&pqkv, g_qkv);
    cudaGetSymbolAddress((void**)&po, g_o);
    bf16 *xh, *xl, *wh3, *wl3, *woh, *wol;
    cudaGetSymbolAddress((void**)&xh, g_xh);
    cudaGetSymbolAddress((void**)&xl, g_xl);
    cudaGetSymbolAddress((void**)&wh3, g_wh3);
    cudaGetSymbolAddress((void**)&wl3, g_wl3);
    cudaGetSymbolAddress((void**)&woh, g_woh);
    cudaGetSymbolAddress((void**)&wol, g_wol);

    cudaFuncSetAttribute(mega_attn_kernel,
                         cudaFuncAttributeMaxDynamicSharedMemorySize,
                         (int)FUSED_SMEM);
    cudaFuncSetAttribute(hgemm3x,
                         cudaFuncAttributeMaxDynamicSharedMemorySize,
                         (int)HG_SMEM);

    const dim3 gqkv(QKV / 128, NT / 128);   // (24, 16) = 384 CTAs
    const dim3 gout(D / 128, NT / 128);     // (8, 16)  = 128 CTAs
    const dim3 gt(32, 32);
    const dim3 gt3(32, 32, 3);
    const dim3 bt(32, 8);
    const int splitBlocks = (NT * D) / (256 * 4);   // 2048

    // launch 0: x split (reused across qkv)
    split_kernel<<<splitBlocks, 256>>>(x, xh, xl);
    // launch 1: batched Wq/Wk/Wv transpose+split
    splitT3_kernel<<<gt3, bt>>>(Wq, Wk, Wv, wh3, wl3);
    // launch 2: Wo transpose+split (independent)
    splitT_kernel<<<gt, bt>>>(Wo, woh, wol);
    // launch 3: ONE fused qkv GEMM (2048 x 3072 x 1024)
    hgemm3x<<<gqkv, 256, HG_SMEM>>>(xh, xl, wh3, wl3, pqkv, NT, QKV, D);
    // launch 4: relq bias table
    relq_kernel<<<dim3(L / 32, BH), 256>>>(relk);
    // launch 5: fused attention
    mega_attn_kernel<<<dim3(L / 32, BH), 256, FUSED_SMEM>>>(relv);
    // launches 6-7: output projection
    split_kernel<<<splitBlocks, 256>>>(po, xh, xl);
    hgemm3x<<<gout, 256, HG_SMEM>>>(xh, xl, woh, wol, out, NT, D, D);
}